// round 14
// baseline (speedup 1.0000x reference)
#include <cuda_runtime.h>
#include <cuda_bf16.h>
#include <math.h>
#include <cstdint>

#define BATCH 2
#define MSRC  4096
#define NTGT  8192
#define CF    512
#define NCLS  20
#define OUTC  512
#define H1    128
#define H2    256
#define CIN   532
#define KNN   3

// Split storage: A2 = [hi | lo] (2*Kpad cols); GEMM remaps logical thirds
// (A: hi,hi,lo / B: hi,lo,hi) onto this storage chunk-by-chunk.
#define KP_SEM  512
#define KP_UP1  544
#define KP_UP2  256
#define K2_SEM  1024
#define K2_UP1  1088
#define K2_UP2  512
#define CPT_SEM 16
#define CPT_UP1 17
#define CPT_UP2 8

typedef unsigned long long ull;

// ---------------- scratch (static device globals; no allocation) ----------------
__device__ __align__(256) float         g_sem_hidden[BATCH * MSRC * H1];
__device__ __align__(256) int           g_knn_idx[BATCH * NTGT * KNN];
__device__ __align__(256) float         g_knn_d[BATCH * NTGT * KNN];
__device__ __align__(256) ull           g_knn_cand[BATCH * NTGT * 2 * KNN];
__device__ __align__(256) __nv_bfloat16 g_a_sem[(size_t)BATCH * MSRC * K2_SEM];
__device__ __align__(256) __nv_bfloat16 g_b_sem1[H1 * K2_SEM];
__device__ __align__(256) __nv_bfloat16 g_a_up1[(size_t)BATCH * NTGT * K2_UP1];
__device__ __align__(256) __nv_bfloat16 g_b_up1[H2 * K2_UP1];
__device__ __align__(256) __nv_bfloat16 g_a_up2[(size_t)BATCH * NTGT * K2_UP2];
__device__ __align__(256) __nv_bfloat16 g_b_up2[OUTC * K2_UP2];

// ---------------- helpers -------------------------------------------------------
__device__ __forceinline__ void bf16_split(float v, __nv_bfloat16& h, __nv_bfloat16& l) {
    h = __float2bfloat16(v);
    l = __float2bfloat16(v - __bfloat162float(h));
}
__device__ __forceinline__ unsigned bf16x2_u32(__nv_bfloat16 a, __nv_bfloat16 b) {
    __nv_bfloat162 t; t.x = a; t.y = b;
    return *(unsigned*)&t;
}
__device__ __forceinline__ void mma_bf16(float& d0, float& d1, float& d2, float& d3,
                                         uint32_t a0, uint32_t a1, uint32_t a2, uint32_t a3,
                                         uint32_t b0, uint32_t b1) {
    asm volatile(
        "mma.sync.aligned.m16n8k16.row.col.f32.bf16.bf16.f32 "
        "{%0,%1,%2,%3}, {%4,%5,%6,%7}, {%8,%9}, {%0,%1,%2,%3};"
        : "+f"(d0), "+f"(d1), "+f"(d2), "+f"(d3)
        : "r"(a0), "r"(a1), "r"(a2), "r"(a3), "r"(b0), "r"(b1));
}
__device__ __forceinline__ uint32_t smem_u32(const void* p) {
    uint32_t a;
    asm("{ .reg .u64 t; cvta.to.shared.u64 t, %1; cvt.u32.u64 %0, t; }"
        : "=r"(a) : "l"(p));
    return a;
}
__device__ __forceinline__ void cp_async16(uint32_t saddr, const void* gptr) {
    asm volatile("cp.async.cg.shared.global [%0], [%1], 16;"
                 :: "r"(saddr), "l"(gptr) : "memory");
}
#define CP_COMMIT() asm volatile("cp.async.commit_group;" ::: "memory")
#define CP_WAIT2()  asm volatile("cp.async.wait_group 2;" ::: "memory")

// chunk remap: logical chunk ch (of 3*CPT) -> stored chunk in [hi|lo]
__device__ __forceinline__ void remap_chunk(int ch, int CPT, int& a_ch, int& b_ch) {
    int c = ch;
    int t = 0;
    if (ch >= 2 * CPT)      { t = 2; c = ch - 2 * CPT; }
    else if (ch >= CPT)     { t = 1; c = ch - CPT; }
    a_ch = (t == 2) ? CPT + c : c;   // A thirds: hi, hi, lo
    b_ch = (t == 1) ? CPT + c : c;   // B thirds: hi, lo, hi
}

// ================= mma.sync split-bf16 GEMM, 64x128 tile, cp.async 4-stage ======
// D[M x N] = sum over 3*CPT logical k32-chunks of A2/B2 (stored [hi|lo]).
// mode 0: write fp32 C.  mode 1: write split bf16 [M][2N] as (h | l).
// Block: 64x128 tile, 256 thr = 8 warps (2x4), warp tile 32x32.
#define SSTR 20                           // words per row (32 bf16 = 16 words + 4 pad)
#define STAGES 4
#define A_BYTES (64 * SSTR * 4)           // 5120 B
#define B_BYTES (128 * SSTR * 4)          // 10240 B
#define STAGE_BYTES (A_BYTES + B_BYTES)   // 15360 B
#define GEMM_SMEM (STAGES * STAGE_BYTES)  // 61440 B

__global__ __launch_bounds__(256, 2)
void gemm_mma_kernel(const __nv_bfloat16* __restrict__ Ap,
                     const __nv_bfloat16* __restrict__ Bp,
                     const float* __restrict__ bias,
                     float* __restrict__ Cf,
                     __nv_bfloat16* __restrict__ Csp,
                     int N, int CPT, int Kstore, int relu, int mode)
{
    extern __shared__ __align__(16) char dsm[];
    const uint32_t sbase = smem_u32(dsm);

    const int tid = threadIdx.x;
    const int wid = tid >> 5;
    const int lane = tid & 31;
    const int g = lane >> 2;
    const int t = lane & 3;

    const int warp_m = wid & 1;        // 0..1 -> rows warp_m*32
    const int warp_n = wid >> 1;       // 0..3 -> cols warp_n*32

    const int rowBase = blockIdx.x * 64;
    const int colBase = blockIdx.y * 128;

    // copy indices: A has 64 rows x 4 segs = 256 (one per thread);
    // B has 128 rows x 4 segs = 512 (two per thread)
    const int crA = tid >> 2, csA = tid & 3;
    const int cr0 = tid >> 2, cs0 = tid & 3;
    const int cr1 = (tid + 256) >> 2;
    const size_t krow = (size_t)Kstore * 2;      // bytes per stored row

    const char* Agp  = (const char*)Ap + (size_t)(rowBase + crA) * krow + csA * 16;
    const char* Bgp  = (const char*)Bp + (size_t)(colBase + cr0) * krow + cs0 * 16;
    const char* Bgp1 = (const char*)Bp + (size_t)(colBase + cr1) * krow + cs0 * 16;

    const uint32_t saA = sbase + (crA * SSTR + csA * 4) * 4;
    const uint32_t sb0 = sbase + A_BYTES + (cr0 * SSTR + cs0 * 4) * 4;
    const uint32_t sb1 = sbase + A_BYTES + (cr1 * SSTR + cs0 * 4) * 4;

    float acc[2][4][4];
#pragma unroll
    for (int i = 0; i < 2; i++)
#pragma unroll
        for (int j = 0; j < 4; j++)
#pragma unroll
            for (int q = 0; q < 4; q++) acc[i][j][q] = 0.0f;

    const int chunks = 3 * CPT;

#define ISSUE_LOAD(CH, STG) do { \
        int _ach, _bch; \
        remap_chunk((CH), CPT, _ach, _bch); \
        const size_t _ao = (size_t)_ach * 64; \
        const size_t _bo = (size_t)_bch * 64; \
        const uint32_t _ss = (STG) * STAGE_BYTES; \
        cp_async16(saA + _ss, Agp + _ao); \
        cp_async16(sb0 + _ss, Bgp + _bo); \
        cp_async16(sb1 + _ss, Bgp1 + _bo); \
    } while (0)

    // prologue: stages 0..2
#pragma unroll
    for (int s = 0; s < STAGES - 1; s++) {
        if (s < chunks) ISSUE_LOAD(s, s);
        CP_COMMIT();
    }

    for (int ch = 0; ch < chunks; ch++) {
        CP_WAIT2();
        __syncthreads();

        const int nc = ch + STAGES - 1;
        if (nc < chunks) ISSUE_LOAD(nc, nc & (STAGES - 1));
        CP_COMMIT();

        const uint32_t* A_ = (const uint32_t*)(dsm + (ch & (STAGES - 1)) * STAGE_BYTES);
        const uint32_t* B_ = A_ + 64 * SSTR;
#pragma unroll
        for (int s = 0; s < 2; s++) {                  // two k16 steps
            const int w0 = s * 8 + t;
            uint32_t afr[2][4];
#pragma unroll
            for (int mt = 0; mt < 2; mt++) {
                const int r = warp_m * 32 + mt * 16 + g;
                afr[mt][0] = A_[r * SSTR + w0];
                afr[mt][1] = A_[(r + 8) * SSTR + w0];
                afr[mt][2] = A_[r * SSTR + w0 + 4];
                afr[mt][3] = A_[(r + 8) * SSTR + w0 + 4];
            }
#pragma unroll
            for (int nt = 0; nt < 4; nt++) {
                const int n = warp_n * 32 + nt * 8 + g;
                const uint32_t b0 = B_[n * SSTR + w0];
                const uint32_t b1 = B_[n * SSTR + w0 + 4];
                mma_bf16(acc[0][nt][0], acc[0][nt][1], acc[0][nt][2], acc[0][nt][3],
                         afr[0][0], afr[0][1], afr[0][2], afr[0][3], b0, b1);
                mma_bf16(acc[1][nt][0], acc[1][nt][1], acc[1][nt][2], acc[1][nt][3],
                         afr[1][0], afr[1][1], afr[1][2], afr[1][3], b0, b1);
            }
        }
    }
#undef ISSUE_LOAD

    // ---------------- epilogue ----------------
#pragma unroll
    for (int mt = 0; mt < 2; mt++) {
        const int r0 = rowBase + warp_m * 32 + mt * 16 + g;
#pragma unroll
        for (int nt = 0; nt < 4; nt++) {
            const int c = colBase + warp_n * 32 + nt * 8 + 2 * t;
            const float bs0 = bias[c], bs1 = bias[c + 1];
            float x0 = acc[mt][nt][0] + bs0;
            float x1 = acc[mt][nt][1] + bs1;
            float x2 = acc[mt][nt][2] + bs0;
            float x3 = acc[mt][nt][3] + bs1;
            if (relu) {
                x0 = fmaxf(x0, 0.0f); x1 = fmaxf(x1, 0.0f);
                x2 = fmaxf(x2, 0.0f); x3 = fmaxf(x3, 0.0f);
            }
            if (mode == 0) {
                float2 v0 = { x0, x1 };
                float2 v1 = { x2, x3 };
                *(float2*)(Cf + (size_t)r0 * N + c) = v0;
                *(float2*)(Cf + (size_t)(r0 + 8) * N + c) = v1;
            } else {
                __nv_bfloat16 h0, l0, h1, l1, h2, l2, h3, l3;
                bf16_split(x0, h0, l0); bf16_split(x1, h1, l1);
                bf16_split(x2, h2, l2); bf16_split(x3, h3, l3);
                const unsigned hu0 = bf16x2_u32(h0, h1), lu0 = bf16x2_u32(l0, l1);
                const unsigned hu1 = bf16x2_u32(h2, h3), lu1 = bf16x2_u32(l2, l3);
                size_t b0 = (size_t)r0 * (2 * N) + c;
                size_t b1 = (size_t)(r0 + 8) * (2 * N) + c;
                *(unsigned*)(Csp + b0)     = hu0;
                *(unsigned*)(Csp + b0 + N) = lu0;
                *(unsigned*)(Csp + b1)     = hu1;
                *(unsigned*)(Csp + b1 + N) = lu1;
            }
        }
    }
}

// ---------------- prep: src_features -> A2_sem [8192][1024] = [hi|lo] -----------
__global__ void prep_a_sem_kernel(const float* __restrict__ feat)
{
    const int m = blockIdx.x;
    const int t = threadIdx.x;
    char* row = (char*)(g_a_sem + (size_t)m * K2_SEM);
    const float4 v = ((const float4*)(feat + (size_t)m * CF))[t];
    __nv_bfloat16 h[4], l[4];
    bf16_split(v.x, h[0], l[0]);
    bf16_split(v.y, h[1], l[1]);
    bf16_split(v.z, h[2], l[2]);
    bf16_split(v.w, h[3], l[3]);
    ull hu = ((ull)bf16x2_u32(h[2], h[3]) << 32) | bf16x2_u32(h[0], h[1]);
    ull lu = ((ull)bf16x2_u32(l[2], l[3]) << 32) | bf16x2_u32(l[0], l[1]);
    *(ull*)(row + 8 * t)            = hu;
    *(ull*)(row + 2 * CF + 8 * t)   = lu;
}

// ---------------- prep: W [K][N] -> B2 [N][2*Kpad] = [hi|lo], zero pad ----------
__global__ void prep_b_kernel(const float* __restrict__ W,
                              __nv_bfloat16* __restrict__ out,
                              int K, int Kpad, int N)
{
    const int n = blockIdx.x;
    __nv_bfloat16* row = out + (size_t)n * (2 * Kpad);
    for (int j = threadIdx.x; j < 2 * Kpad; j += 128) {
        __nv_bfloat16 r = __float2bfloat16(0.0f);
        int half = (j >= Kpad);
        int k = j - half * Kpad;
        if (k < K) {
            __nv_bfloat16 h, l;
            bf16_split(W[(size_t)k * N + n], h, l);
            r = half ? l : h;
        }
        row[j] = r;
    }
}

// ---------------- small SIMT GEMM (N=20 logits) --------------------------------
#define BM 64
#define BN 64
#define BK 16
__global__ void gemm_bias_act_kernel(const float* __restrict__ A,
                                     const float* __restrict__ B,
                                     const float* __restrict__ bias,
                                     float* __restrict__ C,
                                     int M, int N, int K, int relu)
{
    __shared__ float As[BK][BM + 1];
    __shared__ float Bs[BK][BN];
    const int tx = threadIdx.x, ty = threadIdx.y;
    const int tid = ty * 16 + tx;
    const int rowBase = blockIdx.y * BM, colBase = blockIdx.x * BN;
    float acc[4][4];
#pragma unroll
    for (int i = 0; i < 4; i++)
#pragma unroll
        for (int j = 0; j < 4; j++) acc[i][j] = 0.0f;
    const int ar = tid / 16, ac = tid % 16, bn = tid % 64, bk = tid / 64;
    for (int kt = 0; kt < K; kt += BK) {
#pragma unroll
        for (int j = 0; j < 4; j++) {
            int r = ar + j * 16, gr = rowBase + r, gc = kt + ac;
            As[ac][r] = (gc < K) ? A[(size_t)gr * K + gc] : 0.0f;
        }
#pragma unroll
        for (int j = 0; j < 4; j++) {
            int k = bk + j * 4, gk = kt + k, gn = colBase + bn;
            Bs[k][bn] = (gk < K && gn < N) ? B[(size_t)gk * N + gn] : 0.0f;
        }
        __syncthreads();
#pragma unroll
        for (int kk = 0; kk < BK; kk++) {
            float a[4], b[4];
#pragma unroll
            for (int i = 0; i < 4; i++) a[i] = As[kk][ty * 4 + i];
#pragma unroll
            for (int j = 0; j < 4; j++) b[j] = Bs[kk][tx * 4 + j];
#pragma unroll
            for (int i = 0; i < 4; i++)
#pragma unroll
                for (int j = 0; j < 4; j++)
                    acc[i][j] = fmaf(a[i], b[j], acc[i][j]);
        }
        __syncthreads();
    }
#pragma unroll
    for (int i = 0; i < 4; i++) {
        int gr = rowBase + ty * 4 + i;
#pragma unroll
        for (int j = 0; j < 4; j++) {
            int gc = colBase + tx * 4 + j;
            if (gc < N) {
                float v = acc[i][j] + bias[gc];
                if (relu) v = fmaxf(v, 0.0f);
                C[(size_t)gr * N + gc] = v;
            }
        }
    }
}

// ---------------- KNN: two-phase split-source ----------------------------------
#define KH        2048
#define KNN_TPW   4
#define KNN_TGTPB 32

__device__ __forceinline__ ull knn_packkey(float r, int j) {
    unsigned u = __float_as_uint(r);
    u = (u & 0x80000000u) ? ~u : (u | 0x80000000u);
    return ((ull)u << 32) | (unsigned)j;
}
__device__ __forceinline__ float knn_unpackr(ull k) {
    unsigned u = (unsigned)(k >> 32);
    u = (u & 0x80000000u) ? (u & 0x7fffffffu) : ~u;
    return __uint_as_float(u);
}
__device__ __forceinline__ void knn_insert(ull& k0, ull& k1, ull& k2, ull k) {
    if (k < k2) {
        if (k < k1) {
            k2 = k1;
            if (k < k0) { k1 = k0; k0 = k; }
            else        { k1 = k; }
        } else k2 = k;
    }
}
__device__ __forceinline__ void knn_insert_f(float& d0, float& d1, float& d2,
                                             int& i0, int& i1, int& i2,
                                             float r, int j) {
    if (r < d2) {
        if (r < d1) {
            d2 = d1; i2 = i1;
            if (r < d0) { d1 = d0; i1 = i0; d0 = r; i0 = j; }
            else        { d1 = r; i1 = j; }
        } else { d2 = r; i2 = j; }
    }
}

__global__ __launch_bounds__(256)
void knn_part_kernel(const float* __restrict__ src, const float* __restrict__ tgt)
{
    __shared__ float sx[KH], sy[KH], sz[KH];
    const int b = blockIdx.z;
    const int h = blockIdx.y;
    const int jbase = h * KH;
    const float* s = src + ((size_t)b * MSRC + jbase) * 3;
    for (int i = threadIdx.x; i < KH; i += 256) {
        sx[i] = s[3 * i + 0]; sy[i] = s[3 * i + 1]; sz[i] = s[3 * i + 2];
    }
    __syncthreads();

    const int warp = threadIdx.x >> 5, lane = threadIdx.x & 31;
    const int tbase = blockIdx.x * KNN_TGTPB + warp * KNN_TPW;

    float qx[KNN_TPW], qy[KNN_TPW], qz[KNN_TPW];
#pragma unroll
    for (int t = 0; t < KNN_TPW; t++) {
        const float* tp = tgt + ((size_t)b * NTGT + tbase + t) * 3;
        qx[t] = -2.0f * tp[0]; qy[t] = -2.0f * tp[1]; qz[t] = -2.0f * tp[2];
    }

    float d0[KNN_TPW], d1[KNN_TPW], d2[KNN_TPW];
    int   i0[KNN_TPW], i1[KNN_TPW], i2[KNN_TPW];
#pragma unroll
    for (int t = 0; t < KNN_TPW; t++) {
        d0[t] = d1[t] = d2[t] = 1e30f; i0[t] = i1[t] = i2[t] = 0;
    }

    for (int j = lane; j < KH; j += 64) {
        const int ja = j, jb = j + 32;
        const float xa = sx[ja], ya = sy[ja], za = sz[ja];
        const float xb = sx[jb], yb = sy[jb], zb = sz[jb];
        const float s2a = fmaf(xa, xa, fmaf(ya, ya, za * za));
        const float s2b = fmaf(xb, xb, fmaf(yb, yb, zb * zb));
        float ra[KNN_TPW], rb[KNN_TPW];
#pragma unroll
        for (int t = 0; t < KNN_TPW; t++)
            ra[t] = fmaf(xa, qx[t], fmaf(ya, qy[t], fmaf(za, qz[t], s2a)));
#pragma unroll
        for (int t = 0; t < KNN_TPW; t++)
            rb[t] = fmaf(xb, qx[t], fmaf(yb, qy[t], fmaf(zb, qz[t], s2b)));
#pragma unroll
        for (int t = 0; t < KNN_TPW; t++) {
            knn_insert_f(d0[t], d1[t], d2[t], i0[t], i1[t], i2[t], ra[t], ja);
            knn_insert_f(d0[t], d1[t], d2[t], i0[t], i1[t], i2[t], rb[t], jb);
        }
    }

#pragma unroll
    for (int t = 0; t < KNN_TPW; t++) {
        ull k0 = knn_packkey(d0[t], jbase + i0[t]);
        ull k1 = knn_packkey(d1[t], jbase + i1[t]);
        ull k2 = knn_packkey(d2[t], jbase + i2[t]);
#pragma unroll
        for (int off = 16; off; off >>= 1) {
            ull o0 = __shfl_xor_sync(0xffffffffu, k0, off);
            ull o1 = __shfl_xor_sync(0xffffffffu, k1, off);
            ull o2 = __shfl_xor_sync(0xffffffffu, k2, off);
            knn_insert(k0, k1, k2, o0);
            knn_insert(k0, k1, k2, o1);
            knn_insert(k0, k1, k2, o2);
        }
        if (lane == 0) {
            const size_t base = (((size_t)b * NTGT + tbase + t) * 2 + h) * KNN;
            g_knn_cand[base + 0] = k0;
            g_knn_cand[base + 1] = k1;
            g_knn_cand[base + 2] = k2;
        }
    }
}

__global__ void knn_merge_kernel(const float* __restrict__ tgt)
{
    const int row = blockIdx.x * 256 + threadIdx.x;
    if (row >= BATCH * NTGT) return;
    const ull* cand = g_knn_cand + (size_t)row * 2 * KNN;
    ull k0 = cand[0], k1 = cand[1], k2 = cand[2];
    knn_insert(k0, k1, k2, cand[3]);
    knn_insert(k0, k1, k2, cand[4]);
    knn_insert(k0, k1, k2, cand[5]);

    const float* tp = tgt + (size_t)row * 3;
    const float pn = fmaf(tp[0], tp[0], fmaf(tp[1], tp[1], tp[2] * tp[2]));

    const size_t base = (size_t)row * KNN;
    g_knn_idx[base + 0] = (int)(unsigned)k0;
    g_knn_idx[base + 1] = (int)(unsigned)k1;
    g_knn_idx[base + 2] = (int)(unsigned)k2;
    g_knn_d[base + 0] = sqrtf(fmaxf(knn_unpackr(k0) + pn, 0.0f));
    g_knn_d[base + 1] = sqrtf(fmaxf(knn_unpackr(k1) + pn, 0.0f));
    g_knn_d[base + 2] = sqrtf(fmaxf(knn_unpackr(k2) + pn, 0.0f));
}

// ---------------- gather + fuse -> A2_up1 [16384][1088] = [hi|lo] ---------------
__global__ void fuse_kernel(const float* __restrict__ feat,
                            const float* __restrict__ sem)
{
    const int row = blockIdx.x;
    const int b = row / NTGT;
    const size_t base = (size_t)row * KNN;

    const int i0 = g_knn_idx[base + 0];
    const int i1 = g_knn_idx[base + 1];
    const int i2 = g_knn_idx[base + 2];
    const float dd0 = g_knn_d[base + 0];
    const float dd1 = g_knn_d[base + 1];
    const float dd2 = g_knn_d[base + 2];

    const float mn = fminf(dd0, fminf(dd1, dd2));
    const float e0 = expf(mn - dd0);
    const float e1 = expf(mn - dd1);
    const float e2 = expf(mn - dd2);
    const float inv = 1.0f / (e0 + e1 + e2);
    const float w0 = e0 * inv, w1 = e1 * inv, w2 = e2 * inv;

    char* crow = (char*)(g_a_up1 + (size_t)row * K2_UP1);
    const int t = threadIdx.x;

    {
        const float4* f0 = (const float4*)(feat + ((size_t)(b * MSRC + i0)) * CF);
        const float4* f1 = (const float4*)(feat + ((size_t)(b * MSRC + i1)) * CF);
        const float4* f2 = (const float4*)(feat + ((size_t)(b * MSRC + i2)) * CF);
        float4 a0 = f0[t], a1 = f1[t], a2 = f2[t];
        float v[4];
        v[0] = fmaf(w0, a0.x, fmaf(w1, a1.x, w2 * a2.x));
        v[1] = fmaf(w0, a0.y, fmaf(w1, a1.y, w2 * a2.y));
        v[2] = fmaf(w0, a0.z, fmaf(w1, a1.z, w2 * a2.z));
        v[3] = fmaf(w0, a0.w, fmaf(w1, a1.w, w2 * a2.w));
        __nv_bfloat16 h[4], l[4];
#pragma unroll
        for (int q = 0; q < 4; q++) bf16_split(v[q], h[q], l[q]);
        ull hu = ((ull)bf16x2_u32(h[2], h[3]) << 32) | bf16x2_u32(h[0], h[1]);
        ull lu = ((ull)bf16x2_u32(l[2], l[3]) << 32) | bf16x2_u32(l[0], l[1]);
        *(ull*)(crow + 8 * t)                 = hu;
        *(ull*)(crow + 2 * KP_UP1 + 8 * t)    = lu;
    }

    if (t >= 32 && t < 56) {
        int j = t - 32;
        int col = (j < 12) ? (532 + j) : (1076 + (j - 12));
        ((__nv_bfloat16*)crow)[col] = __float2bfloat16(0.0f);
    }

    if (t < 32) {
        int idx[3] = { i0, i1, i2 };
        float accsem = 0.0f;
#pragma unroll
        for (int k = 0; k < 3; k++) {
            const float* srow = sem + ((size_t)(b * MSRC + idx[k])) * NCLS;
            float vv = (t < NCLS) ? srow[t] : -1e30f;
            float m = vv;
#pragma unroll
            for (int off = 16; off; off >>= 1)
                m = fmaxf(m, __shfl_xor_sync(0xffffffffu, m, off));
            float e = (t < NCLS) ? expf(vv - m) : 0.0f;
            float ssum = e;
#pragma unroll
            for (int off = 16; off; off >>= 1)
                ssum += __shfl_xor_sync(0xffffffffu, ssum, off);
            accsem += e / ssum;
        }
        if (t < NCLS) {
            float v = accsem * (1.0f / 3.0f);
            __nv_bfloat16 h, l;
            bf16_split(v, h, l);
            __nv_bfloat16* rw = (__nv_bfloat16*)crow;
            rw[512 + t] = h;
            rw[KP_UP1 + 512 + t] = l;
        }
    }
}

// ---------------- launch --------------------------------------------------------
extern "C" void kernel_launch(void* const* d_in, const int* in_sizes, int n_in,
                              void* d_out, int out_size)
{
    const float* src_points   = (const float*)d_in[0];
    const float* tgt_points   = (const float*)d_in[1];
    const float* src_features = (const float*)d_in[2];
    const float* w_sem1 = (const float*)d_in[3];
    const float* b_sem1 = (const float*)d_in[4];
    const float* w_sem2 = (const float*)d_in[5];
    const float* b_sem2 = (const float*)d_in[6];
    const float* w_up1  = (const float*)d_in[7];
    const float* b_up1  = (const float*)d_in[8];
    const float* w_up2  = (const float*)d_in[9];
    const float* b_up2  = (const float*)d_in[10];

    float* out = (float*)d_out;
    float* sem_out = out + (size_t)BATCH * NTGT * OUTC;

    void* p;
    cudaGetSymbolAddress(&p, g_sem_hidden); float* sem_hidden = (float*)p;
    cudaGetSymbolAddress(&p, g_a_sem);      __nv_bfloat16* a_sem  = (__nv_bfloat16*)p;
    cudaGetSymbolAddress(&p, g_b_sem1);     __nv_bfloat16* bp_sem = (__nv_bfloat16*)p;
    cudaGetSymbolAddress(&p, g_a_up1);      __nv_bfloat16* a_up1  = (__nv_bfloat16*)p;
    cudaGetSymbolAddress(&p, g_b_up1);      __nv_bfloat16* bp_up1 = (__nv_bfloat16*)p;
    cudaGetSymbolAddress(&p, g_a_up2);      __nv_bfloat16* a_up2  = (__nv_bfloat16*)p;
    cudaGetSymbolAddress(&p, g_b_up2);      __nv_bfloat16* bp_up2 = (__nv_bfloat16*)p;

    cudaFuncSetAttribute(gemm_mma_kernel,
                         cudaFuncAttributeMaxDynamicSharedMemorySize, GEMM_SMEM);

    // same launch order: capture slot lands on gemm_mma (sem1)
    prep_b_kernel<<<H1, 128>>>(w_sem1, bp_sem, CF, KP_SEM, H1);          // 0
    prep_b_kernel<<<H2, 128>>>(w_up1, bp_up1, CIN, KP_UP1, H2);          // 1
    prep_a_sem_kernel<<<BATCH * MSRC, 128>>>(src_features);              // 2

    // 3) sem hidden = relu(feat @ w_sem1 + b1)  -> fp32 [8192][128]
    gemm_mma_kernel<<<dim3(BATCH * MSRC / 64, H1 / 128), 256, GEMM_SMEM>>>(
        a_sem, bp_sem, b_sem1, sem_hidden, nullptr, H1, CPT_SEM, K2_SEM, 1, 0);

    // 4) logits = hidden @ w_sem2 + b2 -> d_out tail [8192][20]
    gemm_bias_act_kernel<<<dim3(1, BATCH * MSRC / BM), dim3(16, 16)>>>(
        sem_hidden, w_sem2, b_sem2, sem_out, BATCH * MSRC, NCLS, H1, 0);

    // 5,6) 3-NN two-phase
    knn_part_kernel<<<dim3(NTGT / KNN_TGTPB, 2, BATCH), 256>>>(src_points, tgt_points);
    knn_merge_kernel<<<(BATCH * NTGT + 255) / 256, 256>>>(tgt_points);

    // 7) fuse -> A2_up1 [hi|lo]
    fuse_kernel<<<BATCH * NTGT, 128>>>(src_features, sem_out);

    // 8) prep B for up2
    prep_b_kernel<<<OUTC, 128>>>(w_up2, bp_up2, H2, KP_UP2, OUTC);

    // 9) up hidden = relu(combined @ w_up1 + b)  -> A2_up2 [hi|lo]
    gemm_mma_kernel<<<dim3(BATCH * NTGT / 64, H2 / 128), 256, GEMM_SMEM>>>(
        a_up1, bp_up1, b_up1, nullptr, a_up2, H2, CPT_UP1, K2_UP1, 1, 1);

    // 10) out = up_hidden @ w_up2 + b  -> fp32 [16384][512]
    gemm_mma_kernel<<<dim3(BATCH * NTGT / 64, OUTC / 128), 256, GEMM_SMEM>>>(
        a_up2, bp_up2, b_up2, out, nullptr, OUTC, CPT_UP2, K2_UP2, 0, 0);
}

// round 15
// speedup vs baseline: 1.1049x; 1.1049x over previous
#include <cuda_runtime.h>
#include <cuda_bf16.h>
#include <math.h>
#include <cstdint>

#define BATCH 2
#define MSRC  4096
#define NTGT  8192
#define CF    512
#define NCLS  20
#define OUTC  512
#define H1    128
#define H2    256
#define CIN   532
#define KNN   3

// Split storage: A2 = [hi | lo] (2*Kpad cols); GEMM remaps logical thirds
// (A: hi,hi,lo / B: hi,lo,hi) onto this storage chunk-by-chunk.
#define KP_SEM  512
#define KP_UP1  544
#define KP_UP2  256
#define K2_SEM  1024
#define K2_UP1  1088
#define K2_UP2  512
#define CPT_SEM 16
#define CPT_UP1 17
#define CPT_UP2 8

typedef unsigned long long ull;

// ---------------- scratch (static device globals; no allocation) ----------------
__device__ __align__(256) float         g_sem_hidden[BATCH * MSRC * H1];
__device__ __align__(256) int           g_knn_idx[BATCH * NTGT * KNN];
__device__ __align__(256) float         g_knn_d[BATCH * NTGT * KNN];
__device__ __align__(256) ull           g_knn_cand[BATCH * NTGT * 2 * KNN];
__device__ __align__(256) __nv_bfloat16 g_a_sem[(size_t)BATCH * MSRC * K2_SEM];
__device__ __align__(256) __nv_bfloat16 g_b_sem1[H1 * K2_SEM];
__device__ __align__(256) __nv_bfloat16 g_a_up1[(size_t)BATCH * NTGT * K2_UP1];
__device__ __align__(256) __nv_bfloat16 g_b_up1[H2 * K2_UP1];
__device__ __align__(256) __nv_bfloat16 g_a_up2[(size_t)BATCH * NTGT * K2_UP2];
__device__ __align__(256) __nv_bfloat16 g_b_up2[OUTC * K2_UP2];

// ---------------- helpers -------------------------------------------------------
__device__ __forceinline__ void bf16_split(float v, __nv_bfloat16& h, __nv_bfloat16& l) {
    h = __float2bfloat16(v);
    l = __float2bfloat16(v - __bfloat162float(h));
}
__device__ __forceinline__ unsigned bf16x2_u32(__nv_bfloat16 a, __nv_bfloat16 b) {
    __nv_bfloat162 t; t.x = a; t.y = b;
    return *(unsigned*)&t;
}
__device__ __forceinline__ void mma_bf16(float& d0, float& d1, float& d2, float& d3,
                                         uint32_t a0, uint32_t a1, uint32_t a2, uint32_t a3,
                                         uint32_t b0, uint32_t b1) {
    asm volatile(
        "mma.sync.aligned.m16n8k16.row.col.f32.bf16.bf16.f32 "
        "{%0,%1,%2,%3}, {%4,%5,%6,%7}, {%8,%9}, {%0,%1,%2,%3};"
        : "+f"(d0), "+f"(d1), "+f"(d2), "+f"(d3)
        : "r"(a0), "r"(a1), "r"(a2), "r"(a3), "r"(b0), "r"(b1));
}
__device__ __forceinline__ uint32_t smem_u32(const void* p) {
    uint32_t a;
    asm("{ .reg .u64 t; cvta.to.shared.u64 t, %1; cvt.u32.u64 %0, t; }"
        : "=r"(a) : "l"(p));
    return a;
}
__device__ __forceinline__ void cp_async16(uint32_t saddr, const void* gptr) {
    asm volatile("cp.async.cg.shared.global [%0], [%1], 16;"
                 :: "r"(saddr), "l"(gptr) : "memory");
}
#define CP_COMMIT() asm volatile("cp.async.commit_group;" ::: "memory")
#define CP_WAIT2()  asm volatile("cp.async.wait_group 2;" ::: "memory")

// chunk remap: logical chunk ch (of 3*CPT) -> stored chunk in [hi|lo]
__device__ __forceinline__ void remap_chunk(int ch, int CPT, int& a_ch, int& b_ch) {
    int c = ch;
    int t = 0;
    if (ch >= 2 * CPT)      { t = 2; c = ch - 2 * CPT; }
    else if (ch >= CPT)     { t = 1; c = ch - CPT; }
    a_ch = (t == 2) ? CPT + c : c;   // A thirds: hi, hi, lo
    b_ch = (t == 1) ? CPT + c : c;   // B thirds: hi, lo, hi
}

#define SSTR 20                           // words per row (32 bf16 = 16 words + 4 pad)
#define STAGES 4

// ================= GEMM A: 128x128 tile (for up1/up2; R12-proven) ===============
#define HB128 (128 * SSTR * 4)            // 10240 B per operand
#define STAGE128 (2 * HB128)              // 20480 B
#define SMEM128 (STAGES * STAGE128)       // 81920 B

__global__ __launch_bounds__(256, 2)
void gemm_mma128_kernel(const __nv_bfloat16* __restrict__ Ap,
                        const __nv_bfloat16* __restrict__ Bp,
                        const float* __restrict__ bias,
                        float* __restrict__ Cf,
                        __nv_bfloat16* __restrict__ Csp,
                        int N, int CPT, int Kstore, int relu, int mode)
{
    extern __shared__ __align__(16) char dsm[];
    const uint32_t sbase = smem_u32(dsm);

    const int tid = threadIdx.x;
    const int wid = tid >> 5;
    const int lane = tid & 31;
    const int g = lane >> 2;
    const int t = lane & 3;

    const int warp_m = wid & 3;
    const int warp_n = wid >> 2;

    const int rowBase = blockIdx.x * 128;
    const int colBase = blockIdx.y * 128;

    const int cr0 = tid >> 2, cs0 = tid & 3;
    const int cr1 = (tid + 256) >> 2;
    const size_t krow = (size_t)Kstore * 2;

    const char* Agp  = (const char*)Ap + (size_t)(rowBase + cr0) * krow + cs0 * 16;
    const char* Agp1 = (const char*)Ap + (size_t)(rowBase + cr1) * krow + cs0 * 16;
    const char* Bgp  = (const char*)Bp + (size_t)(colBase + cr0) * krow + cs0 * 16;
    const char* Bgp1 = (const char*)Bp + (size_t)(colBase + cr1) * krow + cs0 * 16;

    const uint32_t sa0 = sbase + (cr0 * SSTR + cs0 * 4) * 4;
    const uint32_t sa1 = sbase + (cr1 * SSTR + cs0 * 4) * 4;
    const uint32_t sb0 = sa0 + HB128;
    const uint32_t sb1 = sa1 + HB128;

    float acc[2][8][4];
#pragma unroll
    for (int i = 0; i < 2; i++)
#pragma unroll
        for (int j = 0; j < 8; j++)
#pragma unroll
            for (int q = 0; q < 4; q++) acc[i][j][q] = 0.0f;

    const int chunks = 3 * CPT;

#define ISSUE128(CH, STG) do { \
        int _ach, _bch; \
        remap_chunk((CH), CPT, _ach, _bch); \
        const size_t _ao = (size_t)_ach * 64; \
        const size_t _bo = (size_t)_bch * 64; \
        const uint32_t _ss = (STG) * STAGE128; \
        cp_async16(sa0 + _ss, Agp + _ao); \
        cp_async16(sa1 + _ss, Agp1 + _ao); \
        cp_async16(sb0 + _ss, Bgp + _bo); \
        cp_async16(sb1 + _ss, Bgp1 + _bo); \
    } while (0)

#pragma unroll
    for (int s = 0; s < STAGES - 1; s++) {
        if (s < chunks) ISSUE128(s, s);
        CP_COMMIT();
    }

    for (int ch = 0; ch < chunks; ch++) {
        CP_WAIT2();
        __syncthreads();

        const int nc = ch + STAGES - 1;
        if (nc < chunks) ISSUE128(nc, nc & (STAGES - 1));
        CP_COMMIT();

        const uint32_t* A_ = (const uint32_t*)(dsm + (ch & (STAGES - 1)) * STAGE128);
        const uint32_t* B_ = A_ + 128 * SSTR;
#pragma unroll
        for (int s = 0; s < 2; s++) {
            const int w0 = s * 8 + t;
            uint32_t afr[2][4];
#pragma unroll
            for (int mt = 0; mt < 2; mt++) {
                const int r = warp_m * 32 + mt * 16 + g;
                afr[mt][0] = A_[r * SSTR + w0];
                afr[mt][1] = A_[(r + 8) * SSTR + w0];
                afr[mt][2] = A_[r * SSTR + w0 + 4];
                afr[mt][3] = A_[(r + 8) * SSTR + w0 + 4];
            }
#pragma unroll
            for (int nt = 0; nt < 8; nt++) {
                const int n = warp_n * 64 + nt * 8 + g;
                const uint32_t b0 = B_[n * SSTR + w0];
                const uint32_t b1 = B_[n * SSTR + w0 + 4];
                mma_bf16(acc[0][nt][0], acc[0][nt][1], acc[0][nt][2], acc[0][nt][3],
                         afr[0][0], afr[0][1], afr[0][2], afr[0][3], b0, b1);
                mma_bf16(acc[1][nt][0], acc[1][nt][1], acc[1][nt][2], acc[1][nt][3],
                         afr[1][0], afr[1][1], afr[1][2], afr[1][3], b0, b1);
            }
        }
    }
#undef ISSUE128

#pragma unroll
    for (int mt = 0; mt < 2; mt++) {
        const int r0 = rowBase + warp_m * 32 + mt * 16 + g;
#pragma unroll
        for (int nt = 0; nt < 8; nt++) {
            const int c = colBase + warp_n * 64 + nt * 8 + 2 * t;
            const float bs0 = bias[c], bs1 = bias[c + 1];
            float x0 = acc[mt][nt][0] + bs0;
            float x1 = acc[mt][nt][1] + bs1;
            float x2 = acc[mt][nt][2] + bs0;
            float x3 = acc[mt][nt][3] + bs1;
            if (relu) {
                x0 = fmaxf(x0, 0.0f); x1 = fmaxf(x1, 0.0f);
                x2 = fmaxf(x2, 0.0f); x3 = fmaxf(x3, 0.0f);
            }
            if (mode == 0) {
                float2 v0 = { x0, x1 };
                float2 v1 = { x2, x3 };
                *(float2*)(Cf + (size_t)r0 * N + c) = v0;
                *(float2*)(Cf + (size_t)(r0 + 8) * N + c) = v1;
            } else {
                __nv_bfloat16 h0, l0, h1, l1, h2, l2, h3, l3;
                bf16_split(x0, h0, l0); bf16_split(x1, h1, l1);
                bf16_split(x2, h2, l2); bf16_split(x3, h3, l3);
                const unsigned hu0 = bf16x2_u32(h0, h1), lu0 = bf16x2_u32(l0, l1);
                const unsigned hu1 = bf16x2_u32(h2, h3), lu1 = bf16x2_u32(l2, l3);
                size_t b0 = (size_t)r0 * (2 * N) + c;
                size_t b1 = (size_t)(r0 + 8) * (2 * N) + c;
                *(unsigned*)(Csp + b0)     = hu0;
                *(unsigned*)(Csp + b0 + N) = lu0;
                *(unsigned*)(Csp + b1)     = hu1;
                *(unsigned*)(Csp + b1 + N) = lu1;
            }
        }
    }
}

// ================= GEMM B: 64x128 tile (for sem1; R14-measured 24.3us) ==========
#define AB64 (64 * SSTR * 4)              // 5120 B
#define BB64 (128 * SSTR * 4)             // 10240 B
#define STAGE64 (AB64 + BB64)             // 15360 B
#define SMEM64 (STAGES * STAGE64)         // 61440 B

__global__ __launch_bounds__(256, 2)
void gemm_mma64_kernel(const __nv_bfloat16* __restrict__ Ap,
                       const __nv_bfloat16* __restrict__ Bp,
                       const float* __restrict__ bias,
                       float* __restrict__ Cf,
                       __nv_bfloat16* __restrict__ Csp,
                       int N, int CPT, int Kstore, int relu, int mode)
{
    extern __shared__ __align__(16) char dsm[];
    const uint32_t sbase = smem_u32(dsm);

    const int tid = threadIdx.x;
    const int wid = tid >> 5;
    const int lane = tid & 31;
    const int g = lane >> 2;
    const int t = lane & 3;

    const int warp_m = wid & 1;        // 0..1 -> rows warp_m*32
    const int warp_n = wid >> 1;       // 0..3 -> cols warp_n*32

    const int rowBase = blockIdx.x * 64;
    const int colBase = blockIdx.y * 128;

    const int crA = tid >> 2, csA = tid & 3;
    const int cr0 = tid >> 2, cs0 = tid & 3;
    const int cr1 = (tid + 256) >> 2;
    const size_t krow = (size_t)Kstore * 2;

    const char* Agp  = (const char*)Ap + (size_t)(rowBase + crA) * krow + csA * 16;
    const char* Bgp  = (const char*)Bp + (size_t)(colBase + cr0) * krow + cs0 * 16;
    const char* Bgp1 = (const char*)Bp + (size_t)(colBase + cr1) * krow + cs0 * 16;

    const uint32_t saA = sbase + (crA * SSTR + csA * 4) * 4;
    const uint32_t sb0 = sbase + AB64 + (cr0 * SSTR + cs0 * 4) * 4;
    const uint32_t sb1 = sbase + AB64 + (cr1 * SSTR + cs0 * 4) * 4;

    float acc[2][4][4];
#pragma unroll
    for (int i = 0; i < 2; i++)
#pragma unroll
        for (int j = 0; j < 4; j++)
#pragma unroll
            for (int q = 0; q < 4; q++) acc[i][j][q] = 0.0f;

    const int chunks = 3 * CPT;

#define ISSUE64(CH, STG) do { \
        int _ach, _bch; \
        remap_chunk((CH), CPT, _ach, _bch); \
        const size_t _ao = (size_t)_ach * 64; \
        const size_t _bo = (size_t)_bch * 64; \
        const uint32_t _ss = (STG) * STAGE64; \
        cp_async16(saA + _ss, Agp + _ao); \
        cp_async16(sb0 + _ss, Bgp + _bo); \
        cp_async16(sb1 + _ss, Bgp1 + _bo); \
    } while (0)

#pragma unroll
    for (int s = 0; s < STAGES - 1; s++) {
        if (s < chunks) ISSUE64(s, s);
        CP_COMMIT();
    }

    for (int ch = 0; ch < chunks; ch++) {
        CP_WAIT2();
        __syncthreads();

        const int nc = ch + STAGES - 1;
        if (nc < chunks) ISSUE64(nc, nc & (STAGES - 1));
        CP_COMMIT();

        const uint32_t* A_ = (const uint32_t*)(dsm + (ch & (STAGES - 1)) * STAGE64);
        const uint32_t* B_ = A_ + 64 * SSTR;
#pragma unroll
        for (int s = 0; s < 2; s++) {
            const int w0 = s * 8 + t;
            uint32_t afr[2][4];
#pragma unroll
            for (int mt = 0; mt < 2; mt++) {
                const int r = warp_m * 32 + mt * 16 + g;
                afr[mt][0] = A_[r * SSTR + w0];
                afr[mt][1] = A_[(r + 8) * SSTR + w0];
                afr[mt][2] = A_[r * SSTR + w0 + 4];
                afr[mt][3] = A_[(r + 8) * SSTR + w0 + 4];
            }
#pragma unroll
            for (int nt = 0; nt < 4; nt++) {
                const int n = warp_n * 32 + nt * 8 + g;
                const uint32_t b0 = B_[n * SSTR + w0];
                const uint32_t b1 = B_[n * SSTR + w0 + 4];
                mma_bf16(acc[0][nt][0], acc[0][nt][1], acc[0][nt][2], acc[0][nt][3],
                         afr[0][0], afr[0][1], afr[0][2], afr[0][3], b0, b1);
                mma_bf16(acc[1][nt][0], acc[1][nt][1], acc[1][nt][2], acc[1][nt][3],
                         afr[1][0], afr[1][1], afr[1][2], afr[1][3], b0, b1);
            }
        }
    }
#undef ISSUE64

#pragma unroll
    for (int mt = 0; mt < 2; mt++) {
        const int r0 = rowBase + warp_m * 32 + mt * 16 + g;
#pragma unroll
        for (int nt = 0; nt < 4; nt++) {
            const int c = colBase + warp_n * 32 + nt * 8 + 2 * t;
            const float bs0 = bias[c], bs1 = bias[c + 1];
            float x0 = acc[mt][nt][0] + bs0;
            float x1 = acc[mt][nt][1] + bs1;
            float x2 = acc[mt][nt][2] + bs0;
            float x3 = acc[mt][nt][3] + bs1;
            if (relu) {
                x0 = fmaxf(x0, 0.0f); x1 = fmaxf(x1, 0.0f);
                x2 = fmaxf(x2, 0.0f); x3 = fmaxf(x3, 0.0f);
            }
            if (mode == 0) {
                float2 v0 = { x0, x1 };
                float2 v1 = { x2, x3 };
                *(float2*)(Cf + (size_t)r0 * N + c) = v0;
                *(float2*)(Cf + (size_t)(r0 + 8) * N + c) = v1;
            } else {
                __nv_bfloat16 h0, l0, h1, l1, h2, l2, h3, l3;
                bf16_split(x0, h0, l0); bf16_split(x1, h1, l1);
                bf16_split(x2, h2, l2); bf16_split(x3, h3, l3);
                const unsigned hu0 = bf16x2_u32(h0, h1), lu0 = bf16x2_u32(l0, l1);
                const unsigned hu1 = bf16x2_u32(h2, h3), lu1 = bf16x2_u32(l2, l3);
                size_t b0 = (size_t)r0 * (2 * N) + c;
                size_t b1 = (size_t)(r0 + 8) * (2 * N) + c;
                *(unsigned*)(Csp + b0)     = hu0;
                *(unsigned*)(Csp + b0 + N) = lu0;
                *(unsigned*)(Csp + b1)     = hu1;
                *(unsigned*)(Csp + b1 + N) = lu1;
            }
        }
    }
}

// ---------------- prep: src_features -> A2_sem [8192][1024] = [hi|lo] -----------
__global__ void prep_a_sem_kernel(const float* __restrict__ feat)
{
    const int m = blockIdx.x;
    const int t = threadIdx.x;
    char* row = (char*)(g_a_sem + (size_t)m * K2_SEM);
    const float4 v = ((const float4*)(feat + (size_t)m * CF))[t];
    __nv_bfloat16 h[4], l[4];
    bf16_split(v.x, h[0], l[0]);
    bf16_split(v.y, h[1], l[1]);
    bf16_split(v.z, h[2], l[2]);
    bf16_split(v.w, h[3], l[3]);
    ull hu = ((ull)bf16x2_u32(h[2], h[3]) << 32) | bf16x2_u32(h[0], h[1]);
    ull lu = ((ull)bf16x2_u32(l[2], l[3]) << 32) | bf16x2_u32(l[0], l[1]);
    *(ull*)(row + 8 * t)            = hu;
    *(ull*)(row + 2 * CF + 8 * t)   = lu;
}

// ---------------- prep: W [K][N] -> B2 [N][2*Kpad] = [hi|lo], zero pad ----------
__global__ void prep_b_kernel(const float* __restrict__ W,
                              __nv_bfloat16* __restrict__ out,
                              int K, int Kpad, int N)
{
    const int n = blockIdx.x;
    __nv_bfloat16* row = out + (size_t)n * (2 * Kpad);
    for (int j = threadIdx.x; j < 2 * Kpad; j += 128) {
        __nv_bfloat16 r = __float2bfloat16(0.0f);
        int half = (j >= Kpad);
        int k = j - half * Kpad;
        if (k < K) {
            __nv_bfloat16 h, l;
            bf16_split(W[(size_t)k * N + n], h, l);
            r = half ? l : h;
        }
        row[j] = r;
    }
}

// ---------------- small SIMT GEMM (N=20 logits) --------------------------------
#define BM 64
#define BN 64
#define BK 16
__global__ void gemm_bias_act_kernel(const float* __restrict__ A,
                                     const float* __restrict__ B,
                                     const float* __restrict__ bias,
                                     float* __restrict__ C,
                                     int M, int N, int K, int relu)
{
    __shared__ float As[BK][BM + 1];
    __shared__ float Bs[BK][BN];
    const int tx = threadIdx.x, ty = threadIdx.y;
    const int tid = ty * 16 + tx;
    const int rowBase = blockIdx.y * BM, colBase = blockIdx.x * BN;
    float acc[4][4];
#pragma unroll
    for (int i = 0; i < 4; i++)
#pragma unroll
        for (int j = 0; j < 4; j++) acc[i][j] = 0.0f;
    const int ar = tid / 16, ac = tid % 16, bn = tid % 64, bk = tid / 64;
    for (int kt = 0; kt < K; kt += BK) {
#pragma unroll
        for (int j = 0; j < 4; j++) {
            int r = ar + j * 16, gr = rowBase + r, gc = kt + ac;
            As[ac][r] = (gc < K) ? A[(size_t)gr * K + gc] : 0.0f;
        }
#pragma unroll
        for (int j = 0; j < 4; j++) {
            int k = bk + j * 4, gk = kt + k, gn = colBase + bn;
            Bs[k][bn] = (gk < K && gn < N) ? B[(size_t)gk * N + gn] : 0.0f;
        }
        __syncthreads();
#pragma unroll
        for (int kk = 0; kk < BK; kk++) {
            float a[4], b[4];
#pragma unroll
            for (int i = 0; i < 4; i++) a[i] = As[kk][ty * 4 + i];
#pragma unroll
            for (int j = 0; j < 4; j++) b[j] = Bs[kk][tx * 4 + j];
#pragma unroll
            for (int i = 0; i < 4; i++)
#pragma unroll
                for (int j = 0; j < 4; j++)
                    acc[i][j] = fmaf(a[i], b[j], acc[i][j]);
        }
        __syncthreads();
    }
#pragma unroll
    for (int i = 0; i < 4; i++) {
        int gr = rowBase + ty * 4 + i;
#pragma unroll
        for (int j = 0; j < 4; j++) {
            int gc = colBase + tx * 4 + j;
            if (gc < N) {
                float v = acc[i][j] + bias[gc];
                if (relu) v = fmaxf(v, 0.0f);
                C[(size_t)gr * N + gc] = v;
            }
        }
    }
}

// ---------------- KNN: two-phase split-source ----------------------------------
#define KH        2048
#define KNN_TPW   4
#define KNN_TGTPB 32

__device__ __forceinline__ ull knn_packkey(float r, int j) {
    unsigned u = __float_as_uint(r);
    u = (u & 0x80000000u) ? ~u : (u | 0x80000000u);
    return ((ull)u << 32) | (unsigned)j;
}
__device__ __forceinline__ float knn_unpackr(ull k) {
    unsigned u = (unsigned)(k >> 32);
    u = (u & 0x80000000u) ? (u & 0x7fffffffu) : ~u;
    return __uint_as_float(u);
}
__device__ __forceinline__ void knn_insert(ull& k0, ull& k1, ull& k2, ull k) {
    if (k < k2) {
        if (k < k1) {
            k2 = k1;
            if (k < k0) { k1 = k0; k0 = k; }
            else        { k1 = k; }
        } else k2 = k;
    }
}
__device__ __forceinline__ void knn_insert_f(float& d0, float& d1, float& d2,
                                             int& i0, int& i1, int& i2,
                                             float r, int j) {
    if (r < d2) {
        if (r < d1) {
            d2 = d1; i2 = i1;
            if (r < d0) { d1 = d0; i1 = i0; d0 = r; i0 = j; }
            else        { d1 = r; i1 = j; }
        } else { d2 = r; i2 = j; }
    }
}

__global__ __launch_bounds__(256)
void knn_part_kernel(const float* __restrict__ src, const float* __restrict__ tgt)
{
    __shared__ float sx[KH], sy[KH], sz[KH];
    const int b = blockIdx.z;
    const int h = blockIdx.y;
    const int jbase = h * KH;
    const float* s = src + ((size_t)b * MSRC + jbase) * 3;
    for (int i = threadIdx.x; i < KH; i += 256) {
        sx[i] = s[3 * i + 0]; sy[i] = s[3 * i + 1]; sz[i] = s[3 * i + 2];
    }
    __syncthreads();

    const int warp = threadIdx.x >> 5, lane = threadIdx.x & 31;
    const int tbase = blockIdx.x * KNN_TGTPB + warp * KNN_TPW;

    float qx[KNN_TPW], qy[KNN_TPW], qz[KNN_TPW];
#pragma unroll
    for (int t = 0; t < KNN_TPW; t++) {
        const float* tp = tgt + ((size_t)b * NTGT + tbase + t) * 3;
        qx[t] = -2.0f * tp[0]; qy[t] = -2.0f * tp[1]; qz[t] = -2.0f * tp[2];
    }

    float d0[KNN_TPW], d1[KNN_TPW], d2[KNN_TPW];
    int   i0[KNN_TPW], i1[KNN_TPW], i2[KNN_TPW];
#pragma unroll
    for (int t = 0; t < KNN_TPW; t++) {
        d0[t] = d1[t] = d2[t] = 1e30f; i0[t] = i1[t] = i2[t] = 0;
    }

    for (int j = lane; j < KH; j += 64) {
        const int ja = j, jb = j + 32;
        const float xa = sx[ja], ya = sy[ja], za = sz[ja];
        const float xb = sx[jb], yb = sy[jb], zb = sz[jb];
        const float s2a = fmaf(xa, xa, fmaf(ya, ya, za * za));
        const float s2b = fmaf(xb, xb, fmaf(yb, yb, zb * zb));
        float ra[KNN_TPW], rb[KNN_TPW];
#pragma unroll
        for (int t = 0; t < KNN_TPW; t++)
            ra[t] = fmaf(xa, qx[t], fmaf(ya, qy[t], fmaf(za, qz[t], s2a)));
#pragma unroll
        for (int t = 0; t < KNN_TPW; t++)
            rb[t] = fmaf(xb, qx[t], fmaf(yb, qy[t], fmaf(zb, qz[t], s2b)));
#pragma unroll
        for (int t = 0; t < KNN_TPW; t++) {
            knn_insert_f(d0[t], d1[t], d2[t], i0[t], i1[t], i2[t], ra[t], ja);
            knn_insert_f(d0[t], d1[t], d2[t], i0[t], i1[t], i2[t], rb[t], jb);
        }
    }

#pragma unroll
    for (int t = 0; t < KNN_TPW; t++) {
        ull k0 = knn_packkey(d0[t], jbase + i0[t]);
        ull k1 = knn_packkey(d1[t], jbase + i1[t]);
        ull k2 = knn_packkey(d2[t], jbase + i2[t]);
#pragma unroll
        for (int off = 16; off; off >>= 1) {
            ull o0 = __shfl_xor_sync(0xffffffffu, k0, off);
            ull o1 = __shfl_xor_sync(0xffffffffu, k1, off);
            ull o2 = __shfl_xor_sync(0xffffffffu, k2, off);
            knn_insert(k0, k1, k2, o0);
            knn_insert(k0, k1, k2, o1);
            knn_insert(k0, k1, k2, o2);
        }
        if (lane == 0) {
            const size_t base = (((size_t)b * NTGT + tbase + t) * 2 + h) * KNN;
            g_knn_cand[base + 0] = k0;
            g_knn_cand[base + 1] = k1;
            g_knn_cand[base + 2] = k2;
        }
    }
}

__global__ void knn_merge_kernel(const float* __restrict__ tgt)
{
    const int row = blockIdx.x * 256 + threadIdx.x;
    if (row >= BATCH * NTGT) return;
    const ull* cand = g_knn_cand + (size_t)row * 2 * KNN;
    ull k0 = cand[0], k1 = cand[1], k2 = cand[2];
    knn_insert(k0, k1, k2, cand[3]);
    knn_insert(k0, k1, k2, cand[4]);
    knn_insert(k0, k1, k2, cand[5]);

    const float* tp = tgt + (size_t)row * 3;
    const float pn = fmaf(tp[0], tp[0], fmaf(tp[1], tp[1], tp[2] * tp[2]));

    const size_t base = (size_t)row * KNN;
    g_knn_idx[base + 0] = (int)(unsigned)k0;
    g_knn_idx[base + 1] = (int)(unsigned)k1;
    g_knn_idx[base + 2] = (int)(unsigned)k2;
    g_knn_d[base + 0] = sqrtf(fmaxf(knn_unpackr(k0) + pn, 0.0f));
    g_knn_d[base + 1] = sqrtf(fmaxf(knn_unpackr(k1) + pn, 0.0f));
    g_knn_d[base + 2] = sqrtf(fmaxf(knn_unpackr(k2) + pn, 0.0f));
}

// ---------------- gather + fuse -> A2_up1 [16384][1088] = [hi|lo] ---------------
__global__ void fuse_kernel(const float* __restrict__ feat,
                            const float* __restrict__ sem)
{
    const int row = blockIdx.x;
    const int b = row / NTGT;
    const size_t base = (size_t)row * KNN;

    const int i0 = g_knn_idx[base + 0];
    const int i1 = g_knn_idx[base + 1];
    const int i2 = g_knn_idx[base + 2];
    const float dd0 = g_knn_d[base + 0];
    const float dd1 = g_knn_d[base + 1];
    const float dd2 = g_knn_d[base + 2];

    const float mn = fminf(dd0, fminf(dd1, dd2));
    const float e0 = expf(mn - dd0);
    const float e1 = expf(mn - dd1);
    const float e2 = expf(mn - dd2);
    const float inv = 1.0f / (e0 + e1 + e2);
    const float w0 = e0 * inv, w1 = e1 * inv, w2 = e2 * inv;

    char* crow = (char*)(g_a_up1 + (size_t)row * K2_UP1);
    const int t = threadIdx.x;

    {
        const float4* f0 = (const float4*)(feat + ((size_t)(b * MSRC + i0)) * CF);
        const float4* f1 = (const float4*)(feat + ((size_t)(b * MSRC + i1)) * CF);
        const float4* f2 = (const float4*)(feat + ((size_t)(b * MSRC + i2)) * CF);
        float4 a0 = f0[t], a1 = f1[t], a2 = f2[t];
        float v[4];
        v[0] = fmaf(w0, a0.x, fmaf(w1, a1.x, w2 * a2.x));
        v[1] = fmaf(w0, a0.y, fmaf(w1, a1.y, w2 * a2.y));
        v[2] = fmaf(w0, a0.z, fmaf(w1, a1.z, w2 * a2.z));
        v[3] = fmaf(w0, a0.w, fmaf(w1, a1.w, w2 * a2.w));
        __nv_bfloat16 h[4], l[4];
#pragma unroll
        for (int q = 0; q < 4; q++) bf16_split(v[q], h[q], l[q]);
        ull hu = ((ull)bf16x2_u32(h[2], h[3]) << 32) | bf16x2_u32(h[0], h[1]);
        ull lu = ((ull)bf16x2_u32(l[2], l[3]) << 32) | bf16x2_u32(l[0], l[1]);
        *(ull*)(crow + 8 * t)                 = hu;
        *(ull*)(crow + 2 * KP_UP1 + 8 * t)    = lu;
    }

    if (t >= 32 && t < 56) {
        int j = t - 32;
        int col = (j < 12) ? (532 + j) : (1076 + (j - 12));
        ((__nv_bfloat16*)crow)[col] = __float2bfloat16(0.0f);
    }

    if (t < 32) {
        int idx[3] = { i0, i1, i2 };
        float accsem = 0.0f;
#pragma unroll
        for (int k = 0; k < 3; k++) {
            const float* srow = sem + ((size_t)(b * MSRC + idx[k])) * NCLS;
            float vv = (t < NCLS) ? srow[t] : -1e30f;
            float m = vv;
#pragma unroll
            for (int off = 16; off; off >>= 1)
                m = fmaxf(m, __shfl_xor_sync(0xffffffffu, m, off));
            float e = (t < NCLS) ? expf(vv - m) : 0.0f;
            float ssum = e;
#pragma unroll
            for (int off = 16; off; off >>= 1)
                ssum += __shfl_xor_sync(0xffffffffu, ssum, off);
            accsem += e / ssum;
        }
        if (t < NCLS) {
            float v = accsem * (1.0f / 3.0f);
            __nv_bfloat16 h, l;
            bf16_split(v, h, l);
            __nv_bfloat16* rw = (__nv_bfloat16*)crow;
            rw[512 + t] = h;
            rw[KP_UP1 + 512 + t] = l;
        }
    }
}

// ---------------- launch --------------------------------------------------------
extern "C" void kernel_launch(void* const* d_in, const int* in_sizes, int n_in,
                              void* d_out, int out_size)
{
    const float* src_points   = (const float*)d_in[0];
    const float* tgt_points   = (const float*)d_in[1];
    const float* src_features = (const float*)d_in[2];
    const float* w_sem1 = (const float*)d_in[3];
    const float* b_sem1 = (const float*)d_in[4];
    const float* w_sem2 = (const float*)d_in[5];
    const float* b_sem2 = (const float*)d_in[6];
    const float* w_up1  = (const float*)d_in[7];
    const float* b_up1  = (const float*)d_in[8];
    const float* w_up2  = (const float*)d_in[9];
    const float* b_up2  = (const float*)d_in[10];

    float* out = (float*)d_out;
    float* sem_out = out + (size_t)BATCH * NTGT * OUTC;

    void* p;
    cudaGetSymbolAddress(&p, g_sem_hidden); float* sem_hidden = (float*)p;
    cudaGetSymbolAddress(&p, g_a_sem);      __nv_bfloat16* a_sem  = (__nv_bfloat16*)p;
    cudaGetSymbolAddress(&p, g_b_sem1);     __nv_bfloat16* bp_sem = (__nv_bfloat16*)p;
    cudaGetSymbolAddress(&p, g_a_up1);      __nv_bfloat16* a_up1  = (__nv_bfloat16*)p;
    cudaGetSymbolAddress(&p, g_b_up1);      __nv_bfloat16* bp_up1 = (__nv_bfloat16*)p;
    cudaGetSymbolAddress(&p, g_a_up2);      __nv_bfloat16* a_up2  = (__nv_bfloat16*)p;
    cudaGetSymbolAddress(&p, g_b_up2);      __nv_bfloat16* bp_up2 = (__nv_bfloat16*)p;

    cudaFuncSetAttribute(gemm_mma64_kernel,
                         cudaFuncAttributeMaxDynamicSharedMemorySize, SMEM64);
    cudaFuncSetAttribute(gemm_mma128_kernel,
                         cudaFuncAttributeMaxDynamicSharedMemorySize, SMEM128);

    prep_b_kernel<<<H1, 128>>>(w_sem1, bp_sem, CF, KP_SEM, H1);          // 0
    prep_b_kernel<<<H2, 128>>>(w_up1, bp_up1, CIN, KP_UP1, H2);          // 1
    prep_a_sem_kernel<<<BATCH * MSRC, 128>>>(src_features);              // 2

    // 3) sem hidden = relu(feat @ w_sem1 + b1)  -> fp32 [8192][128] (64-tile)
    gemm_mma64_kernel<<<dim3(BATCH * MSRC / 64, H1 / 128), 256, SMEM64>>>(
        a_sem, bp_sem, b_sem1, sem_hidden, nullptr, H1, CPT_SEM, K2_SEM, 1, 0);

    // 4) logits = hidden @ w_sem2 + b2 -> d_out tail [8192][20]
    gemm_bias_act_kernel<<<dim3(1, BATCH * MSRC / BM), dim3(16, 16)>>>(
        sem_hidden, w_sem2, b_sem2, sem_out, BATCH * MSRC, NCLS, H1, 0);

    // 5,6) 3-NN two-phase
    knn_part_kernel<<<dim3(NTGT / KNN_TGTPB, 2, BATCH), 256>>>(src_points, tgt_points);
    knn_merge_kernel<<<(BATCH * NTGT + 255) / 256, 256>>>(tgt_points);

    // 7) fuse -> A2_up1 [hi|lo]
    fuse_kernel<<<BATCH * NTGT, 128>>>(src_features, sem_out);

    // 8) prep B for up2
    prep_b_kernel<<<OUTC, 128>>>(w_up2, bp_up2, H2, KP_UP2, OUTC);

    // 9) up hidden = relu(combined @ w_up1 + b)  -> A2_up2 [hi|lo] (128-tile)
    gemm_mma128_kernel<<<dim3(BATCH * NTGT / 128, H2 / 128), 256, SMEM128>>>(
        a_up1, bp_up1, b_up1, nullptr, a_up2, H2, CPT_UP1, K2_UP1, 1, 1);

    // 10) out = up_hidden @ w_up2 + b  -> fp32 [16384][512] (128-tile)
    gemm_mma128_kernel<<<dim3(BATCH * NTGT / 128, OUTC / 128), 256, SMEM128>>>(
        a_up2, bp_up2, b_up2, out, nullptr, OUTC, CPT_UP2, K2_UP2, 0, 0);
}

// round 16
// speedup vs baseline: 1.1348x; 1.0271x over previous
#include <cuda_runtime.h>
#include <cuda_bf16.h>
#include <math.h>
#include <cstdint>

#define BATCH 2
#define MSRC  4096
#define NTGT  8192
#define CF    512
#define NCLS  20
#define OUTC  512
#define H1    128
#define H2    256
#define CIN   532
#define KNN   3

#define KP_SEM  512
#define KP_UP1  544
#define KP_UP2  256
#define K2_SEM  1024
#define K2_UP1  1088
#define K2_UP2  512
#define CPT_SEM 16
#define CPT_UP1 17
#define CPT_UP2 8

typedef unsigned long long ull;

// ---------------- scratch (static device globals; no allocation) ----------------
__device__ __align__(256) float         g_sem_hidden[BATCH * MSRC * H1];
__device__ __align__(256) int           g_knn_idx[BATCH * NTGT * KNN];
__device__ __align__(256) float         g_knn_d[BATCH * NTGT * KNN];
__device__ __align__(256) ull           g_knn_cand[BATCH * NTGT * 2 * KNN];
__device__ __align__(256) __nv_bfloat16 g_a_sem[(size_t)BATCH * MSRC * K2_SEM];
__device__ __align__(256) __nv_bfloat16 g_b_sem1[H1 * K2_SEM];
__device__ __align__(256) __nv_bfloat16 g_a_up1[(size_t)BATCH * NTGT * K2_UP1];
__device__ __align__(256) __nv_bfloat16 g_b_up1[H2 * K2_UP1];
__device__ __align__(256) __nv_bfloat16 g_a_up2[(size_t)BATCH * NTGT * K2_UP2];
__device__ __align__(256) __nv_bfloat16 g_b_up2[OUTC * K2_UP2];

// ---------------- helpers -------------------------------------------------------
__device__ __forceinline__ void bf16_split(float v, __nv_bfloat16& h, __nv_bfloat16& l) {
    h = __float2bfloat16(v);
    l = __float2bfloat16(v - __bfloat162float(h));
}
__device__ __forceinline__ unsigned bf16x2_u32(__nv_bfloat16 a, __nv_bfloat16 b) {
    __nv_bfloat162 t; t.x = a; t.y = b;
    return *(unsigned*)&t;
}
__device__ __forceinline__ void mma_bf16(float& d0, float& d1, float& d2, float& d3,
                                         uint32_t a0, uint32_t a1, uint32_t a2, uint32_t a3,
                                         uint32_t b0, uint32_t b1) {
    asm volatile(
        "mma.sync.aligned.m16n8k16.row.col.f32.bf16.bf16.f32 "
        "{%0,%1,%2,%3}, {%4,%5,%6,%7}, {%8,%9}, {%0,%1,%2,%3};"
        : "+f"(d0), "+f"(d1), "+f"(d2), "+f"(d3)
        : "r"(a0), "r"(a1), "r"(a2), "r"(a3), "r"(b0), "r"(b1));
}
__device__ __forceinline__ void ldsm_x4(uint32_t& r0, uint32_t& r1,
                                        uint32_t& r2, uint32_t& r3, uint32_t saddr) {
    asm volatile("ldmatrix.sync.aligned.m8n8.x4.shared.b16 {%0,%1,%2,%3}, [%4];"
                 : "=r"(r0), "=r"(r1), "=r"(r2), "=r"(r3) : "r"(saddr));
}
__device__ __forceinline__ uint32_t smem_u32(const void* p) {
    uint32_t a;
    asm("{ .reg .u64 t; cvta.to.shared.u64 t, %1; cvt.u32.u64 %0, t; }"
        : "=r"(a) : "l"(p));
    return a;
}
__device__ __forceinline__ void cp_async16(uint32_t saddr, const void* gptr) {
    asm volatile("cp.async.cg.shared.global [%0], [%1], 16;"
                 :: "r"(saddr), "l"(gptr) : "memory");
}
#define CP_COMMIT() asm volatile("cp.async.commit_group;" ::: "memory")
#define CP_WAIT2()  asm volatile("cp.async.wait_group 2;" ::: "memory")

// chunk remap: logical chunk ch (of 3*CPT) -> stored chunk in [hi|lo]
__device__ __forceinline__ void remap_chunk(int ch, int CPT, int& a_ch, int& b_ch) {
    int c = ch;
    int t = 0;
    if (ch >= 2 * CPT)      { t = 2; c = ch - 2 * CPT; }
    else if (ch >= CPT)     { t = 1; c = ch - CPT; }
    a_ch = (t == 2) ? CPT + c : c;   // A thirds: hi, hi, lo
    b_ch = (t == 1) ? CPT + c : c;   // B thirds: hi, lo, hi
}

#define SSTR 20                           // words per row (32 bf16 = 16 words + 4 pad)
#define SROWB (SSTR * 4)                  // 80 bytes per row
#define STAGES 4

// ================= GEMM A: 128x128 tile (up1/up2) ===============================
#define HB128 (128 * SSTR * 4)            // 10240 B per operand
#define STAGE128 (2 * HB128)              // 20480 B
#define SMEM128 (STAGES * STAGE128)       // 81920 B

__global__ __launch_bounds__(256, 2)
void gemm_mma128_kernel(const __nv_bfloat16* __restrict__ Ap,
                        const __nv_bfloat16* __restrict__ Bp,
                        const float* __restrict__ bias,
                        float* __restrict__ Cf,
                        __nv_bfloat16* __restrict__ Csp,
                        int N, int CPT, int Kstore, int relu, int mode)
{
    extern __shared__ __align__(16) char dsm[];
    const uint32_t sbase = smem_u32(dsm);

    const int tid = threadIdx.x;
    const int wid = tid >> 5;
    const int lane = tid & 31;
    const int g = lane >> 2;
    const int t = lane & 3;
    const int lane15 = lane & 15;
    const int laneHi = lane >> 4;

    const int warp_m = wid & 3;
    const int warp_n = wid >> 2;

    const int rowBase = blockIdx.x * 128;
    const int colBase = blockIdx.y * 128;

    const int cr0 = tid >> 2, cs0 = tid & 3;
    const int cr1 = (tid + 256) >> 2;
    const size_t krow = (size_t)Kstore * 2;

    const char* Agp  = (const char*)Ap + (size_t)(rowBase + cr0) * krow + cs0 * 16;
    const char* Agp1 = (const char*)Ap + (size_t)(rowBase + cr1) * krow + cs0 * 16;
    const char* Bgp  = (const char*)Bp + (size_t)(colBase + cr0) * krow + cs0 * 16;
    const char* Bgp1 = (const char*)Bp + (size_t)(colBase + cr1) * krow + cs0 * 16;

    const uint32_t sa0 = sbase + (cr0 * SSTR + cs0 * 4) * 4;
    const uint32_t sa1 = sbase + (cr1 * SSTR + cs0 * 4) * 4;
    const uint32_t sb0 = sa0 + HB128;
    const uint32_t sb1 = sa1 + HB128;

    // ldmatrix per-lane offsets (within a stage)
    uint32_t aoff[2], boff[4];
#pragma unroll
    for (int mt = 0; mt < 2; mt++)
        aoff[mt] = (warp_m * 32 + mt * 16 + lane15) * SROWB + laneHi * 16;
#pragma unroll
    for (int p = 0; p < 4; p++)
        boff[p] = HB128 + (warp_n * 64 + p * 16 + lane15) * SROWB + laneHi * 16;

    float acc[2][8][4];
#pragma unroll
    for (int i = 0; i < 2; i++)
#pragma unroll
        for (int j = 0; j < 8; j++)
#pragma unroll
            for (int q = 0; q < 4; q++) acc[i][j][q] = 0.0f;

    const int chunks = 3 * CPT;

#define ISSUE128(CH, STG) do { \
        int _ach, _bch; \
        remap_chunk((CH), CPT, _ach, _bch); \
        const size_t _ao = (size_t)_ach * 64; \
        const size_t _bo = (size_t)_bch * 64; \
        const uint32_t _ss = (STG) * STAGE128; \
        cp_async16(sa0 + _ss, Agp + _ao); \
        cp_async16(sa1 + _ss, Agp1 + _ao); \
        cp_async16(sb0 + _ss, Bgp + _bo); \
        cp_async16(sb1 + _ss, Bgp1 + _bo); \
    } while (0)

#pragma unroll
    for (int s = 0; s < STAGES - 1; s++) {
        if (s < chunks) ISSUE128(s, s);
        CP_COMMIT();
    }

    for (int ch = 0; ch < chunks; ch++) {
        CP_WAIT2();
        __syncthreads();

        const int nc = ch + STAGES - 1;
        if (nc < chunks) ISSUE128(nc, nc & (STAGES - 1));
        CP_COMMIT();

        const uint32_t stg = sbase + (ch & (STAGES - 1)) * STAGE128;
#pragma unroll
        for (int s = 0; s < 2; s++) {
            const uint32_t so = s * 32;
            uint32_t af[8], bf[16];
            ldsm_x4(af[0], af[1], af[2], af[3], stg + aoff[0] + so);
            ldsm_x4(af[4], af[5], af[6], af[7], stg + aoff[1] + so);
#pragma unroll
            for (int p = 0; p < 4; p++)
                ldsm_x4(bf[4 * p], bf[4 * p + 1], bf[4 * p + 2], bf[4 * p + 3],
                        stg + boff[p] + so);
#pragma unroll
            for (int nt = 0; nt < 8; nt++) {
                const int p = nt >> 1, o = nt & 1;
                const uint32_t b0 = bf[4 * p + o];
                const uint32_t b1 = bf[4 * p + 2 + o];
                mma_bf16(acc[0][nt][0], acc[0][nt][1], acc[0][nt][2], acc[0][nt][3],
                         af[0], af[1], af[2], af[3], b0, b1);
                mma_bf16(acc[1][nt][0], acc[1][nt][1], acc[1][nt][2], acc[1][nt][3],
                         af[4], af[5], af[6], af[7], b0, b1);
            }
        }
    }
#undef ISSUE128

#pragma unroll
    for (int mt = 0; mt < 2; mt++) {
        const int r0 = rowBase + warp_m * 32 + mt * 16 + g;
#pragma unroll
        for (int nt = 0; nt < 8; nt++) {
            const int c = colBase + warp_n * 64 + nt * 8 + 2 * t;
            const float bs0 = bias[c], bs1 = bias[c + 1];
            float x0 = acc[mt][nt][0] + bs0;
            float x1 = acc[mt][nt][1] + bs1;
            float x2 = acc[mt][nt][2] + bs0;
            float x3 = acc[mt][nt][3] + bs1;
            if (relu) {
                x0 = fmaxf(x0, 0.0f); x1 = fmaxf(x1, 0.0f);
                x2 = fmaxf(x2, 0.0f); x3 = fmaxf(x3, 0.0f);
            }
            if (mode == 0) {
                float2 v0 = { x0, x1 };
                float2 v1 = { x2, x3 };
                *(float2*)(Cf + (size_t)r0 * N + c) = v0;
                *(float2*)(Cf + (size_t)(r0 + 8) * N + c) = v1;
            } else {
                __nv_bfloat16 h0, l0, h1, l1, h2, l2, h3, l3;
                bf16_split(x0, h0, l0); bf16_split(x1, h1, l1);
                bf16_split(x2, h2, l2); bf16_split(x3, h3, l3);
                const unsigned hu0 = bf16x2_u32(h0, h1), lu0 = bf16x2_u32(l0, l1);
                const unsigned hu1 = bf16x2_u32(h2, h3), lu1 = bf16x2_u32(l2, l3);
                size_t b0 = (size_t)r0 * (2 * N) + c;
                size_t b1 = (size_t)(r0 + 8) * (2 * N) + c;
                *(unsigned*)(Csp + b0)     = hu0;
                *(unsigned*)(Csp + b0 + N) = lu0;
                *(unsigned*)(Csp + b1)     = hu1;
                *(unsigned*)(Csp + b1 + N) = lu1;
            }
        }
    }
}

// ================= GEMM B: 64x128 tile (sem1) ===================================
#define AB64 (64 * SSTR * 4)              // 5120 B
#define BB64 (128 * SSTR * 4)             // 10240 B
#define STAGE64 (AB64 + BB64)             // 15360 B
#define SMEM64 (STAGES * STAGE64)         // 61440 B

__global__ __launch_bounds__(256, 2)
void gemm_mma64_kernel(const __nv_bfloat16* __restrict__ Ap,
                       const __nv_bfloat16* __restrict__ Bp,
                       const float* __restrict__ bias,
                       float* __restrict__ Cf,
                       __nv_bfloat16* __restrict__ Csp,
                       int N, int CPT, int Kstore, int relu, int mode)
{
    extern __shared__ __align__(16) char dsm[];
    const uint32_t sbase = smem_u32(dsm);

    const int tid = threadIdx.x;
    const int wid = tid >> 5;
    const int lane = tid & 31;
    const int g = lane >> 2;
    const int t = lane & 3;
    const int lane15 = lane & 15;
    const int laneHi = lane >> 4;

    const int warp_m = wid & 1;        // 0..1 -> rows warp_m*32
    const int warp_n = wid >> 1;       // 0..3 -> cols warp_n*32

    const int rowBase = blockIdx.x * 64;
    const int colBase = blockIdx.y * 128;

    const int crA = tid >> 2, csA = tid & 3;
    const int cr0 = tid >> 2, cs0 = tid & 3;
    const int cr1 = (tid + 256) >> 2;
    const size_t krow = (size_t)Kstore * 2;

    const char* Agp  = (const char*)Ap + (size_t)(rowBase + crA) * krow + csA * 16;
    const char* Bgp  = (const char*)Bp + (size_t)(colBase + cr0) * krow + cs0 * 16;
    const char* Bgp1 = (const char*)Bp + (size_t)(colBase + cr1) * krow + cs0 * 16;

    const uint32_t saA = sbase + (crA * SSTR + csA * 4) * 4;
    const uint32_t sb0 = sbase + AB64 + (cr0 * SSTR + cs0 * 4) * 4;
    const uint32_t sb1 = sbase + AB64 + (cr1 * SSTR + cs0 * 4) * 4;

    uint32_t aoff[2], boff[2];
#pragma unroll
    for (int mt = 0; mt < 2; mt++)
        aoff[mt] = (warp_m * 32 + mt * 16 + lane15) * SROWB + laneHi * 16;
#pragma unroll
    for (int p = 0; p < 2; p++)
        boff[p] = AB64 + (warp_n * 32 + p * 16 + lane15) * SROWB + laneHi * 16;

    float acc[2][4][4];
#pragma unroll
    for (int i = 0; i < 2; i++)
#pragma unroll
        for (int j = 0; j < 4; j++)
#pragma unroll
            for (int q = 0; q < 4; q++) acc[i][j][q] = 0.0f;

    const int chunks = 3 * CPT;

#define ISSUE64(CH, STG) do { \
        int _ach, _bch; \
        remap_chunk((CH), CPT, _ach, _bch); \
        const size_t _ao = (size_t)_ach * 64; \
        const size_t _bo = (size_t)_bch * 64; \
        const uint32_t _ss = (STG) * STAGE64; \
        cp_async16(saA + _ss, Agp + _ao); \
        cp_async16(sb0 + _ss, Bgp + _bo); \
        cp_async16(sb1 + _ss, Bgp1 + _bo); \
    } while (0)

#pragma unroll
    for (int s = 0; s < STAGES - 1; s++) {
        if (s < chunks) ISSUE64(s, s);
        CP_COMMIT();
    }

    for (int ch = 0; ch < chunks; ch++) {
        CP_WAIT2();
        __syncthreads();

        const int nc = ch + STAGES - 1;
        if (nc < chunks) ISSUE64(nc, nc & (STAGES - 1));
        CP_COMMIT();

        const uint32_t stg = sbase + (ch & (STAGES - 1)) * STAGE64;
#pragma unroll
        for (int s = 0; s < 2; s++) {
            const uint32_t so = s * 32;
            uint32_t af[8], bf[8];
            ldsm_x4(af[0], af[1], af[2], af[3], stg + aoff[0] + so);
            ldsm_x4(af[4], af[5], af[6], af[7], stg + aoff[1] + so);
            ldsm_x4(bf[0], bf[1], bf[2], bf[3], stg + boff[0] + so);
            ldsm_x4(bf[4], bf[5], bf[6], bf[7], stg + boff[1] + so);
#pragma unroll
            for (int nt = 0; nt < 4; nt++) {
                const int p = nt >> 1, o = nt & 1;
                const uint32_t b0 = bf[4 * p + o];
                const uint32_t b1 = bf[4 * p + 2 + o];
                mma_bf16(acc[0][nt][0], acc[0][nt][1], acc[0][nt][2], acc[0][nt][3],
                         af[0], af[1], af[2], af[3], b0, b1);
                mma_bf16(acc[1][nt][0], acc[1][nt][1], acc[1][nt][2], acc[1][nt][3],
                         af[4], af[5], af[6], af[7], b0, b1);
            }
        }
    }
#undef ISSUE64

#pragma unroll
    for (int mt = 0; mt < 2; mt++) {
        const int r0 = rowBase + warp_m * 32 + mt * 16 + g;
#pragma unroll
        for (int nt = 0; nt < 4; nt++) {
            const int c = colBase + warp_n * 32 + nt * 8 + 2 * t;
            const float bs0 = bias[c], bs1 = bias[c + 1];
            float x0 = acc[mt][nt][0] + bs0;
            float x1 = acc[mt][nt][1] + bs1;
            float x2 = acc[mt][nt][2] + bs0;
            float x3 = acc[mt][nt][3] + bs1;
            if (relu) {
                x0 = fmaxf(x0, 0.0f); x1 = fmaxf(x1, 0.0f);
                x2 = fmaxf(x2, 0.0f); x3 = fmaxf(x3, 0.0f);
            }
            if (mode == 0) {
                float2 v0 = { x0, x1 };
                float2 v1 = { x2, x3 };
                *(float2*)(Cf + (size_t)r0 * N + c) = v0;
                *(float2*)(Cf + (size_t)(r0 + 8) * N + c) = v1;
            } else {
                __nv_bfloat16 h0, l0, h1, l1, h2, l2, h3, l3;
                bf16_split(x0, h0, l0); bf16_split(x1, h1, l1);
                bf16_split(x2, h2, l2); bf16_split(x3, h3, l3);
                const unsigned hu0 = bf16x2_u32(h0, h1), lu0 = bf16x2_u32(l0, l1);
                const unsigned hu1 = bf16x2_u32(h2, h3), lu1 = bf16x2_u32(l2, l3);
                size_t b0 = (size_t)r0 * (2 * N) + c;
                size_t b1 = (size_t)(r0 + 8) * (2 * N) + c;
                *(unsigned*)(Csp + b0)     = hu0;
                *(unsigned*)(Csp + b0 + N) = lu0;
                *(unsigned*)(Csp + b1)     = hu1;
                *(unsigned*)(Csp + b1 + N) = lu1;
            }
        }
    }
}

// ---------------- prep: src_features -> A2_sem [8192][1024] = [hi|lo] -----------
__global__ void prep_a_sem_kernel(const float* __restrict__ feat)
{
    const int m = blockIdx.x;
    const int t = threadIdx.x;
    char* row = (char*)(g_a_sem + (size_t)m * K2_SEM);
    const float4 v = ((const float4*)(feat + (size_t)m * CF))[t];
    __nv_bfloat16 h[4], l[4];
    bf16_split(v.x, h[0], l[0]);
    bf16_split(v.y, h[1], l[1]);
    bf16_split(v.z, h[2], l[2]);
    bf16_split(v.w, h[3], l[3]);
    ull hu = ((ull)bf16x2_u32(h[2], h[3]) << 32) | bf16x2_u32(h[0], h[1]);
    ull lu = ((ull)bf16x2_u32(l[2], l[3]) << 32) | bf16x2_u32(l[0], l[1]);
    *(ull*)(row + 8 * t)            = hu;
    *(ull*)(row + 2 * CF + 8 * t)   = lu;
}

// ---------------- prep: W [K][N] -> B2 [N][2*Kpad] = [hi|lo], zero pad ----------
__global__ void prep_b_kernel(const float* __restrict__ W,
                              __nv_bfloat16* __restrict__ out,
                              int K, int Kpad, int N)
{
    const int n = blockIdx.x;
    __nv_bfloat16* row = out + (size_t)n * (2 * Kpad);
    for (int j = threadIdx.x; j < 2 * Kpad; j += 128) {
        __nv_bfloat16 r = __float2bfloat16(0.0f);
        int half = (j >= Kpad);
        int k = j - half * Kpad;
        if (k < K) {
            __nv_bfloat16 h, l;
            bf16_split(W[(size_t)k * N + n], h, l);
            r = half ? l : h;
        }
        row[j] = r;
    }
}

// ---------------- small SIMT GEMM (N=20 logits) --------------------------------
#define BM 64
#define BN 64
#define BK 16
__global__ void gemm_bias_act_kernel(const float* __restrict__ A,
                                     const float* __restrict__ B,
                                     const float* __restrict__ bias,
                                     float* __restrict__ C,
                                     int M, int N, int K, int relu)
{
    __shared__ float As[BK][BM + 1];
    __shared__ float Bs[BK][BN];
    const int tx = threadIdx.x, ty = threadIdx.y;
    const int tid = ty * 16 + tx;
    const int rowBase = blockIdx.y * BM, colBase = blockIdx.x * BN;
    float acc[4][4];
#pragma unroll
    for (int i = 0; i < 4; i++)
#pragma unroll
        for (int j = 0; j < 4; j++) acc[i][j] = 0.0f;
    const int ar = tid / 16, ac = tid % 16, bn = tid % 64, bk = tid / 64;
    for (int kt = 0; kt < K; kt += BK) {
#pragma unroll
        for (int j = 0; j < 4; j++) {
            int r = ar + j * 16, gr = rowBase + r, gc = kt + ac;
            As[ac][r] = (gc < K) ? A[(size_t)gr * K + gc] : 0.0f;
        }
#pragma unroll
        for (int j = 0; j < 4; j++) {
            int k = bk + j * 4, gk = kt + k, gn = colBase + bn;
            Bs[k][bn] = (gk < K && gn < N) ? B[(size_t)gk * N + gn] : 0.0f;
        }
        __syncthreads();
#pragma unroll
        for (int kk = 0; kk < BK; kk++) {
            float a[4], b[4];
#pragma unroll
            for (int i = 0; i < 4; i++) a[i] = As[kk][ty * 4 + i];
#pragma unroll
            for (int j = 0; j < 4; j++) b[j] = Bs[kk][tx * 4 + j];
#pragma unroll
            for (int i = 0; i < 4; i++)
#pragma unroll
                for (int j = 0; j < 4; j++)
                    acc[i][j] = fmaf(a[i], b[j], acc[i][j]);
        }
        __syncthreads();
    }
#pragma unroll
    for (int i = 0; i < 4; i++) {
        int gr = rowBase + ty * 4 + i;
#pragma unroll
        for (int j = 0; j < 4; j++) {
            int gc = colBase + tx * 4 + j;
            if (gc < N) {
                float v = acc[i][j] + bias[gc];
                if (relu) v = fmaxf(v, 0.0f);
                C[(size_t)gr * N + gc] = v;
            }
        }
    }
}

// ---------------- KNN: two-phase split-source ----------------------------------
#define KH        2048
#define KNN_TPW   4
#define KNN_TGTPB 32

__device__ __forceinline__ ull knn_packkey(float r, int j) {
    unsigned u = __float_as_uint(r);
    u = (u & 0x80000000u) ? ~u : (u | 0x80000000u);
    return ((ull)u << 32) | (unsigned)j;
}
__device__ __forceinline__ float knn_unpackr(ull k) {
    unsigned u = (unsigned)(k >> 32);
    u = (u & 0x80000000u) ? (u & 0x7fffffffu) : ~u;
    return __uint_as_float(u);
}
__device__ __forceinline__ void knn_insert(ull& k0, ull& k1, ull& k2, ull k) {
    if (k < k2) {
        if (k < k1) {
            k2 = k1;
            if (k < k0) { k1 = k0; k0 = k; }
            else        { k1 = k; }
        } else k2 = k;
    }
}
__device__ __forceinline__ void knn_insert_f(float& d0, float& d1, float& d2,
                                             int& i0, int& i1, int& i2,
                                             float r, int j) {
    if (r < d2) {
        if (r < d1) {
            d2 = d1; i2 = i1;
            if (r < d0) { d1 = d0; i1 = i0; d0 = r; i0 = j; }
            else        { d1 = r; i1 = j; }
        } else { d2 = r; i2 = j; }
    }
}

__global__ __launch_bounds__(256)
void knn_part_kernel(const float* __restrict__ src, const float* __restrict__ tgt)
{
    __shared__ float sx[KH], sy[KH], sz[KH];
    const int b = blockIdx.z;
    const int h = blockIdx.y;
    const int jbase = h * KH;
    const float* s = src + ((size_t)b * MSRC + jbase) * 3;
    for (int i = threadIdx.x; i < KH; i += 256) {
        sx[i] = s[3 * i + 0]; sy[i] = s[3 * i + 1]; sz[i] = s[3 * i + 2];
    }
    __syncthreads();

    const int warp = threadIdx.x >> 5, lane = threadIdx.x & 31;
    const int tbase = blockIdx.x * KNN_TGTPB + warp * KNN_TPW;

    float qx[KNN_TPW], qy[KNN_TPW], qz[KNN_TPW];
#pragma unroll
    for (int t = 0; t < KNN_TPW; t++) {
        const float* tp = tgt + ((size_t)b * NTGT + tbase + t) * 3;
        qx[t] = -2.0f * tp[0]; qy[t] = -2.0f * tp[1]; qz[t] = -2.0f * tp[2];
    }

    float d0[KNN_TPW], d1[KNN_TPW], d2[KNN_TPW];
    int   i0[KNN_TPW], i1[KNN_TPW], i2[KNN_TPW];
#pragma unroll
    for (int t = 0; t < KNN_TPW; t++) {
        d0[t] = d1[t] = d2[t] = 1e30f; i0[t] = i1[t] = i2[t] = 0;
    }

    for (int j = lane; j < KH; j += 64) {
        const int ja = j, jb = j + 32;
        const float xa = sx[ja], ya = sy[ja], za = sz[ja];
        const float xb = sx[jb], yb = sy[jb], zb = sz[jb];
        const float s2a = fmaf(xa, xa, fmaf(ya, ya, za * za));
        const float s2b = fmaf(xb, xb, fmaf(yb, yb, zb * zb));
        float ra[KNN_TPW], rb[KNN_TPW];
#pragma unroll
        for (int t = 0; t < KNN_TPW; t++)
            ra[t] = fmaf(xa, qx[t], fmaf(ya, qy[t], fmaf(za, qz[t], s2a)));
#pragma unroll
        for (int t = 0; t < KNN_TPW; t++)
            rb[t] = fmaf(xb, qx[t], fmaf(yb, qy[t], fmaf(zb, qz[t], s2b)));
#pragma unroll
        for (int t = 0; t < KNN_TPW; t++) {
            knn_insert_f(d0[t], d1[t], d2[t], i0[t], i1[t], i2[t], ra[t], ja);
            knn_insert_f(d0[t], d1[t], d2[t], i0[t], i1[t], i2[t], rb[t], jb);
        }
    }

#pragma unroll
    for (int t = 0; t < KNN_TPW; t++) {
        ull k0 = knn_packkey(d0[t], jbase + i0[t]);
        ull k1 = knn_packkey(d1[t], jbase + i1[t]);
        ull k2 = knn_packkey(d2[t], jbase + i2[t]);
#pragma unroll
        for (int off = 16; off; off >>= 1) {
            ull o0 = __shfl_xor_sync(0xffffffffu, k0, off);
            ull o1 = __shfl_xor_sync(0xffffffffu, k1, off);
            ull o2 = __shfl_xor_sync(0xffffffffu, k2, off);
            knn_insert(k0, k1, k2, o0);
            knn_insert(k0, k1, k2, o1);
            knn_insert(k0, k1, k2, o2);
        }
        if (lane == 0) {
            const size_t base = (((size_t)b * NTGT + tbase + t) * 2 + h) * KNN;
            g_knn_cand[base + 0] = k0;
            g_knn_cand[base + 1] = k1;
            g_knn_cand[base + 2] = k2;
        }
    }
}

__global__ void knn_merge_kernel(const float* __restrict__ tgt)
{
    const int row = blockIdx.x * 256 + threadIdx.x;
    if (row >= BATCH * NTGT) return;
    const ull* cand = g_knn_cand + (size_t)row * 2 * KNN;
    ull k0 = cand[0], k1 = cand[1], k2 = cand[2];
    knn_insert(k0, k1, k2, cand[3]);
    knn_insert(k0, k1, k2, cand[4]);
    knn_insert(k0, k1, k2, cand[5]);

    const float* tp = tgt + (size_t)row * 3;
    const float pn = fmaf(tp[0], tp[0], fmaf(tp[1], tp[1], tp[2] * tp[2]));

    const size_t base = (size_t)row * KNN;
    g_knn_idx[base + 0] = (int)(unsigned)k0;
    g_knn_idx[base + 1] = (int)(unsigned)k1;
    g_knn_idx[base + 2] = (int)(unsigned)k2;
    g_knn_d[base + 0] = sqrtf(fmaxf(knn_unpackr(k0) + pn, 0.0f));
    g_knn_d[base + 1] = sqrtf(fmaxf(knn_unpackr(k1) + pn, 0.0f));
    g_knn_d[base + 2] = sqrtf(fmaxf(knn_unpackr(k2) + pn, 0.0f));
}

// ---------------- gather + fuse -> A2_up1 [16384][1088] = [hi|lo] ---------------
__global__ void fuse_kernel(const float* __restrict__ feat,
                            const float* __restrict__ sem)
{
    const int row = blockIdx.x;
    const int b = row / NTGT;
    const size_t base = (size_t)row * KNN;

    const int i0 = g_knn_idx[base + 0];
    const int i1 = g_knn_idx[base + 1];
    const int i2 = g_knn_idx[base + 2];
    const float dd0 = g_knn_d[base + 0];
    const float dd1 = g_knn_d[base + 1];
    const float dd2 = g_knn_d[base + 2];

    const float mn = fminf(dd0, fminf(dd1, dd2));
    const float e0 = expf(mn - dd0);
    const float e1 = expf(mn - dd1);
    const float e2 = expf(mn - dd2);
    const float inv = 1.0f / (e0 + e1 + e2);
    const float w0 = e0 * inv, w1 = e1 * inv, w2 = e2 * inv;

    char* crow = (char*)(g_a_up1 + (size_t)row * K2_UP1);
    const int t = threadIdx.x;

    {
        const float4* f0 = (const float4*)(feat + ((size_t)(b * MSRC + i0)) * CF);
        const float4* f1 = (const float4*)(feat + ((size_t)(b * MSRC + i1)) * CF);
        const float4* f2 = (const float4*)(feat + ((size_t)(b * MSRC + i2)) * CF);
        float4 a0 = f0[t], a1 = f1[t], a2 = f2[t];
        float v[4];
        v[0] = fmaf(w0, a0.x, fmaf(w1, a1.x, w2 * a2.x));
        v[1] = fmaf(w0, a0.y, fmaf(w1, a1.y, w2 * a2.y));
        v[2] = fmaf(w0, a0.z, fmaf(w1, a1.z, w2 * a2.z));
        v[3] = fmaf(w0, a0.w, fmaf(w1, a1.w, w2 * a2.w));
        __nv_bfloat16 h[4], l[4];
#pragma unroll
        for (int q = 0; q < 4; q++) bf16_split(v[q], h[q], l[q]);
        ull hu = ((ull)bf16x2_u32(h[2], h[3]) << 32) | bf16x2_u32(h[0], h[1]);
        ull lu = ((ull)bf16x2_u32(l[2], l[3]) << 32) | bf16x2_u32(l[0], l[1]);
        *(ull*)(crow + 8 * t)                 = hu;
        *(ull*)(crow + 2 * KP_UP1 + 8 * t)    = lu;
    }

    if (t >= 32 && t < 56) {
        int j = t - 32;
        int col = (j < 12) ? (532 + j) : (1076 + (j - 12));
        ((__nv_bfloat16*)crow)[col] = __float2bfloat16(0.0f);
    }

    if (t < 32) {
        int idx[3] = { i0, i1, i2 };
        float accsem = 0.0f;
#pragma unroll
        for (int k = 0; k < 3; k++) {
            const float* srow = sem + ((size_t)(b * MSRC + idx[k])) * NCLS;
            float vv = (t < NCLS) ? srow[t] : -1e30f;
            float m = vv;
#pragma unroll
            for (int off = 16; off; off >>= 1)
                m = fmaxf(m, __shfl_xor_sync(0xffffffffu, m, off));
            float e = (t < NCLS) ? expf(vv - m) : 0.0f;
            float ssum = e;
#pragma unroll
            for (int off = 16; off; off >>= 1)
                ssum += __shfl_xor_sync(0xffffffffu, ssum, off);
            accsem += e / ssum;
        }
        if (t < NCLS) {
            float v = accsem * (1.0f / 3.0f);
            __nv_bfloat16 h, l;
            bf16_split(v, h, l);
            __nv_bfloat16* rw = (__nv_bfloat16*)crow;
            rw[512 + t] = h;
            rw[KP_UP1 + 512 + t] = l;
        }
    }
}

// ---------------- launch --------------------------------------------------------
extern "C" void kernel_launch(void* const* d_in, const int* in_sizes, int n_in,
                              void* d_out, int out_size)
{
    const float* src_points   = (const float*)d_in[0];
    const float* tgt_points   = (const float*)d_in[1];
    const float* src_features = (const float*)d_in[2];
    const float* w_sem1 = (const float*)d_in[3];
    const float* b_sem1 = (const float*)d_in[4];
    const float* w_sem2 = (const float*)d_in[5];
    const float* b_sem2 = (const float*)d_in[6];
    const float* w_up1  = (const float*)d_in[7];
    const float* b_up1  = (const float*)d_in[8];
    const float* w_up2  = (const float*)d_in[9];
    const float* b_up2  = (const float*)d_in[10];

    float* out = (float*)d_out;
    float* sem_out = out + (size_t)BATCH * NTGT * OUTC;

    void* p;
    cudaGetSymbolAddress(&p, g_sem_hidden); float* sem_hidden = (float*)p;
    cudaGetSymbolAddress(&p, g_a_sem);      __nv_bfloat16* a_sem  = (__nv_bfloat16*)p;
    cudaGetSymbolAddress(&p, g_b_sem1);     __nv_bfloat16* bp_sem = (__nv_bfloat16*)p;
    cudaGetSymbolAddress(&p, g_a_up1);      __nv_bfloat16* a_up1  = (__nv_bfloat16*)p;
    cudaGetSymbolAddress(&p, g_b_up1);      __nv_bfloat16* bp_up1 = (__nv_bfloat16*)p;
    cudaGetSymbolAddress(&p, g_a_up2);      __nv_bfloat16* a_up2  = (__nv_bfloat16*)p;
    cudaGetSymbolAddress(&p, g_b_up2);      __nv_bfloat16* bp_up2 = (__nv_bfloat16*)p;

    cudaFuncSetAttribute(gemm_mma64_kernel,
                         cudaFuncAttributeMaxDynamicSharedMemorySize, SMEM64);
    cudaFuncSetAttribute(gemm_mma128_kernel,
                         cudaFuncAttributeMaxDynamicSharedMemorySize, SMEM128);

    prep_b_kernel<<<H1, 128>>>(w_sem1, bp_sem, CF, KP_SEM, H1);          // 0
    prep_b_kernel<<<H2, 128>>>(w_up1, bp_up1, CIN, KP_UP1, H2);          // 1
    prep_a_sem_kernel<<<BATCH * MSRC, 128>>>(src_features);              // 2

    // 3) sem hidden = relu(feat @ w_sem1 + b1)  -> fp32 [8192][128] (64-tile)
    gemm_mma64_kernel<<<dim3(BATCH * MSRC / 64, H1 / 128), 256, SMEM64>>>(
        a_sem, bp_sem, b_sem1, sem_hidden, nullptr, H1, CPT_SEM, K2_SEM, 1, 0);

    // 4) logits = hidden @ w_sem2 + b2 -> d_out tail [8192][20]
    gemm_bias_act_kernel<<<dim3(1, BATCH * MSRC / BM), dim3(16, 16)>>>(
        sem_hidden, w_sem2, b_sem2, sem_out, BATCH * MSRC, NCLS, H1, 0);

    // 5,6) 3-NN two-phase
    knn_part_kernel<<<dim3(NTGT / KNN_TGTPB, 2, BATCH), 256>>>(src_points, tgt_points);
    knn_merge_kernel<<<(BATCH * NTGT + 255) / 256, 256>>>(tgt_points);

    // 7) fuse -> A2_up1 [hi|lo]
    fuse_kernel<<<BATCH * NTGT, 128>>>(src_features, sem_out);

    // 8) prep B for up2
    prep_b_kernel<<<OUTC, 128>>>(w_up2, bp_up2, H2, KP_UP2, OUTC);

    // 9) up hidden = relu(combined @ w_up1 + b)  -> A2_up2 [hi|lo] (128-tile)
    gemm_mma128_kernel<<<dim3(BATCH * NTGT / 128, H2 / 128), 256, SMEM128>>>(
        a_up1, bp_up1, b_up1, nullptr, a_up2, H2, CPT_UP1, K2_UP1, 1, 1);

    // 10) out = up_hidden @ w_up2 + b  -> fp32 [16384][512] (128-tile)
    gemm_mma128_kernel<<<dim3(BATCH * NTGT / 128, OUTC / 128), 256, SMEM128>>>(
        a_up2, bp_up2, b_up2, out, nullptr, OUTC, CPT_UP2, K2_UP2, 0, 0);
}